// round 2
// baseline (speedup 1.0000x reference)
#include <cuda_runtime.h>
#include <cstdint>

// Problem shape (fixed by setup_inputs): N=16384, D=1024, K=1024
#define MAX_N 16384
#define MAX_K 1024
#define MAX_D 1024

#define BM 128
#define BN 128
#define BK 8
#define TM 8
#define TN 8

// Scratch (static __device__ arrays — no allocation allowed)
__device__ float              g_sums[MAX_K * MAX_D];   // batch cluster sums [K, D]
__device__ int                g_msum[MAX_K];           // per-cluster counts
__device__ float              g_c2h [MAX_K];           // 0.5 * ||c_k||^2
__device__ int                g_labels[MAX_N];         // argmin labels

// ---------------------------------------------------------------------------
// 0.5 * ||c_k||^2 per center. grid = K, block = 128.
// ---------------------------------------------------------------------------
__global__ void c2h_kernel(const float* __restrict__ C, int D) {
    int k = blockIdx.x;
    const float4* row = (const float4*)(C + (size_t)k * D);
    float s = 0.f;
    for (int i = threadIdx.x; i < D / 4; i += blockDim.x) {
        float4 v = row[i];
        s += v.x * v.x + v.y * v.y + v.z * v.z + v.w * v.w;
    }
    #pragma unroll
    for (int o = 16; o > 0; o >>= 1) s += __shfl_xor_sync(0xFFFFFFFFu, s, o);
    __shared__ float ws[32];
    int lane = threadIdx.x & 31, w = threadIdx.x >> 5;
    if (lane == 0) ws[w] = s;
    __syncthreads();
    if (threadIdx.x == 0) {
        float t = 0.f;
        int nw = blockDim.x >> 5;
        for (int i = 0; i < nw; i++) t += ws[i];
        g_c2h[k] = 0.5f * t;
    }
}

// ---------------------------------------------------------------------------
// Zero scratch. grid covers K*D.
// ---------------------------------------------------------------------------
__global__ void zero_kernel(int n_sums, int K) {
    int i = blockIdx.x * blockDim.x + threadIdx.x;
    if (i < n_sums) g_sums[i] = 0.f;
    if (i < K)      g_msum[i] = 0;
}

// ---------------------------------------------------------------------------
// Fused SGEMM + argmax.  score[i,k] = x_i . c_k - 0.5||c_k||^2; labels = argmax.
// One block per 128-row tile of X; the block loops over all K column tiles.
// Per-thread running best kept as an order-preserving 64-bit key:
//   key = (flip(float) << 32) | (K-1-k)   -> max-key == (max score, then min k)
// which matches jnp.argmin's first-min tie-break exactly.
// ---------------------------------------------------------------------------
__global__ __launch_bounds__(256, 1)
void gemm_argmax_kernel(const float* __restrict__ X, const float* __restrict__ C,
                        int N, int K, int D) {
    __shared__ float As[BK][BM];
    __shared__ float Bs[BK][BN];

    const int tid = threadIdx.x;
    const int tx  = tid & 15;    // column group (0..15)
    const int ty  = tid >> 4;    // row group    (0..15)
    const int rowBase = blockIdx.x * BM;

    // global-load mapping: 256 threads move 128 rows x 8 cols as 256 float4
    const int lrow  = tid >> 1;        // 0..127
    const int lcol4 = (tid & 1) * 4;   // 0 or 4

    unsigned long long best[TM];
    #pragma unroll
    for (int i = 0; i < TM; i++) best[i] = 0ULL;

    for (int kn = 0; kn < K; kn += BN) {
        float acc[TM][TN];
        #pragma unroll
        for (int i = 0; i < TM; i++)
            #pragma unroll
            for (int j = 0; j < TN; j++) acc[i][j] = 0.f;

        for (int kd = 0; kd < D; kd += BK) {
            float4 a4 = *(const float4*)(X + (size_t)(rowBase + lrow) * D + kd + lcol4);
            As[lcol4 + 0][lrow] = a4.x;
            As[lcol4 + 1][lrow] = a4.y;
            As[lcol4 + 2][lrow] = a4.z;
            As[lcol4 + 3][lrow] = a4.w;
            float4 b4 = *(const float4*)(C + (size_t)(kn + lrow) * D + kd + lcol4);
            Bs[lcol4 + 0][lrow] = b4.x;
            Bs[lcol4 + 1][lrow] = b4.y;
            Bs[lcol4 + 2][lrow] = b4.z;
            Bs[lcol4 + 3][lrow] = b4.w;
            __syncthreads();

            #pragma unroll
            for (int kk = 0; kk < BK; kk++) {
                float a[TM], b[TN];
                float4 av0 = *(const float4*)&As[kk][ty * TM];
                float4 av1 = *(const float4*)&As[kk][ty * TM + 4];
                a[0] = av0.x; a[1] = av0.y; a[2] = av0.z; a[3] = av0.w;
                a[4] = av1.x; a[5] = av1.y; a[6] = av1.z; a[7] = av1.w;
                float4 bv0 = *(const float4*)&Bs[kk][tx * TN];
                float4 bv1 = *(const float4*)&Bs[kk][tx * TN + 4];
                b[0] = bv0.x; b[1] = bv0.y; b[2] = bv0.z; b[3] = bv0.w;
                b[4] = bv1.x; b[5] = bv1.y; b[6] = bv1.z; b[7] = bv1.w;
                #pragma unroll
                for (int i = 0; i < TM; i++)
                    #pragma unroll
                    for (int j = 0; j < TN; j++)
                        acc[i][j] = fmaf(a[i], b[j], acc[i][j]);
            }
            __syncthreads();
        }

        // fold this column tile into the per-row running best
        #pragma unroll
        for (int j = 0; j < TN; j++) {
            int col = kn + tx * TN + j;
            float h = g_c2h[col];
            #pragma unroll
            for (int i = 0; i < TM; i++) {
                float v = acc[i][j] - h;
                unsigned u = __float_as_uint(v);
                u ^= (u & 0x80000000u) ? 0xFFFFFFFFu : 0x80000000u;
                unsigned long long key =
                    ((unsigned long long)u << 32) | (unsigned)(K - 1 - col);
                if (key > best[i]) best[i] = key;
            }
        }
    }

    // reduce the 16 column-group threads per row
    __shared__ unsigned long long sbest[BM];
    if (tid < BM) sbest[tid] = 0ULL;
    __syncthreads();
    #pragma unroll
    for (int i = 0; i < TM; i++)
        atomicMax(&sbest[ty * TM + i], best[i]);
    __syncthreads();
    if (tid < BM) {
        int k = K - 1 - (int)(sbest[tid] & 0xFFFFFFFFULL);
        g_labels[rowBase + tid] = k;
    }
}

// ---------------------------------------------------------------------------
// Segmented sum: sums[label[i]] += x_i ; msum[label[i]] += 1.
// grid = N, block = 256 (D/4 float4 per row -> one pass).
// ---------------------------------------------------------------------------
__global__ void accum_kernel(const float* __restrict__ X, int D) {
    int i = blockIdx.x;
    int lab = g_labels[i];
    const float4* row = (const float4*)(X + (size_t)i * D);
    float* dst = g_sums + (size_t)lab * D;
    for (int c = threadIdx.x; c < D / 4; c += blockDim.x) {
        float4 v = row[c];
        atomicAdd(&dst[4 * c + 0], v.x);
        atomicAdd(&dst[4 * c + 1], v.y);
        atomicAdd(&dst[4 * c + 2], v.z);
        atomicAdd(&dst[4 * c + 3], v.w);
    }
    if (threadIdx.x == 0) atomicAdd(&g_msum[lab], 1);
}

// ---------------------------------------------------------------------------
// EMA update. grid = K, block = 256.
// ---------------------------------------------------------------------------
__global__ void finalize_kernel(const float* __restrict__ centers,
                                const int* __restrict__ count,
                                float* __restrict__ out, int D) {
    int k = blockIdx.x;
    int cnt = g_msum[k];
    const float4* crow = (const float4*)(centers + (size_t)k * D);
    float4* orow = (float4*)(out + (size_t)k * D);
    if (cnt == 0) {
        for (int c = threadIdx.x; c < D / 4; c += blockDim.x) orow[c] = crow[c];
        return;
    }
    const float4* srow = (const float4*)(g_sums + (size_t)k * D);
    float cc  = (float)count[k];
    float cnf = (float)cnt;
    float cc_new = 0.5f * cc + 0.5f * cnf;       // CENTER_LR = 0.5
    float lr  = 1.0f / (cc_new + 1.0f);
    float om  = 1.0f - lr;
    float bscale = lr / cnf;                     // lr * (1/mask_sum)
    for (int c = threadIdx.x; c < D / 4; c += blockDim.x) {
        float4 cv = crow[c];
        float4 sv = srow[c];
        float4 o;
        o.x = om * cv.x + bscale * sv.x;
        o.y = om * cv.y + bscale * sv.y;
        o.z = om * cv.z + bscale * sv.z;
        o.w = om * cv.w + bscale * sv.w;
        orow[c] = o;
    }
}

// ---------------------------------------------------------------------------
extern "C" void kernel_launch(void* const* d_in, const int* in_sizes, int n_in,
                              void* d_out, int out_size) {
    const float* X     = (const float*)d_in[0];   // embedded [N, D]
    const float* C     = (const float*)d_in[1];   // centers  [K, D]
    const int*   count = (const int*)d_in[2];     // count    [K]
    float*       out   = (float*)d_out;           // new_centers [K, D]

    const int K = in_sizes[2];
    const int D = in_sizes[1] / K;
    const int N = in_sizes[0] / D;

    zero_kernel<<<(K * D + 255) / 256, 256>>>(K * D, K);
    c2h_kernel<<<K, 128>>>(C, D);
    gemm_argmax_kernel<<<N / BM, 256>>>(X, C, N, K, D);
    accum_kernel<<<N, 256>>>(X, D);
    finalize_kernel<<<K, 256>>>(C, count, out, D);
}

// round 3
// speedup vs baseline: 1.0031x; 1.0031x over previous
#include <cuda_runtime.h>
#include <cstdint>

// Problem shape (fixed by setup_inputs): N=16384, D=1024, K=1024
#define MAX_N 16384
#define MAX_K 1024
#define MAX_D 1024

#define BM 128
#define BN 128
#define BK 8
#define TM 8
#define TN 8

// Scratch (static __device__ arrays — no allocation allowed)
__device__ float              g_sums[MAX_K * MAX_D];   // batch cluster sums [K, D]
__device__ int                g_msum[MAX_K];           // per-cluster counts
__device__ float              g_c2h [MAX_K];           // 0.5 * ||c_k||^2
__device__ int                g_labels[MAX_N];         // argmin labels

// ---------------------------------------------------------------------------
// 0.5 * ||c_k||^2 per center. grid = K, block = 128.
// ---------------------------------------------------------------------------
__global__ void c2h_kernel(const float* __restrict__ C, int D) {
    int k = blockIdx.x;
    const float4* row = (const float4*)(C + (size_t)k * D);
    float s = 0.f;
    for (int i = threadIdx.x; i < D / 4; i += blockDim.x) {
        float4 v = row[i];
        s += v.x * v.x + v.y * v.y + v.z * v.z + v.w * v.w;
    }
    #pragma unroll
    for (int o = 16; o > 0; o >>= 1) s += __shfl_xor_sync(0xFFFFFFFFu, s, o);
    __shared__ float ws[32];
    int lane = threadIdx.x & 31, w = threadIdx.x >> 5;
    if (lane == 0) ws[w] = s;
    __syncthreads();
    if (threadIdx.x == 0) {
        float t = 0.f;
        int nw = blockDim.x >> 5;
        for (int i = 0; i < nw; i++) t += ws[i];
        g_c2h[k] = 0.5f * t;
    }
}

// ---------------------------------------------------------------------------
// Zero scratch. grid covers K*D.
// ---------------------------------------------------------------------------
__global__ void zero_kernel(int n_sums, int K) {
    int i = blockIdx.x * blockDim.x + threadIdx.x;
    if (i < n_sums) g_sums[i] = 0.f;
    if (i < K)      g_msum[i] = 0;
}

// ---------------------------------------------------------------------------
// Fused SGEMM + argmax.  score[i,k] = x_i . c_k - 0.5||c_k||^2; labels = argmax.
// One block per 128-row tile of X; the block loops over all K column tiles.
// Per-thread running best kept as an order-preserving 64-bit key:
//   key = (flip(float) << 32) | (K-1-k)   -> max-key == (max score, then min k)
// which matches jnp.argmin's first-min tie-break exactly.
// ---------------------------------------------------------------------------
__global__ __launch_bounds__(256, 1)
void gemm_argmax_kernel(const float* __restrict__ X, const float* __restrict__ C,
                        int N, int K, int D) {
    __shared__ float As[BK][BM];
    __shared__ float Bs[BK][BN];

    const int tid = threadIdx.x;
    const int tx  = tid & 15;    // column group (0..15)
    const int ty  = tid >> 4;    // row group    (0..15)
    const int rowBase = blockIdx.x * BM;

    // global-load mapping: 256 threads move 128 rows x 8 cols as 256 float4
    const int lrow  = tid >> 1;        // 0..127
    const int lcol4 = (tid & 1) * 4;   // 0 or 4

    unsigned long long best[TM];
    #pragma unroll
    for (int i = 0; i < TM; i++) best[i] = 0ULL;

    for (int kn = 0; kn < K; kn += BN) {
        float acc[TM][TN];
        #pragma unroll
        for (int i = 0; i < TM; i++)
            #pragma unroll
            for (int j = 0; j < TN; j++) acc[i][j] = 0.f;

        for (int kd = 0; kd < D; kd += BK) {
            float4 a4 = *(const float4*)(X + (size_t)(rowBase + lrow) * D + kd + lcol4);
            As[lcol4 + 0][lrow] = a4.x;
            As[lcol4 + 1][lrow] = a4.y;
            As[lcol4 + 2][lrow] = a4.z;
            As[lcol4 + 3][lrow] = a4.w;
            float4 b4 = *(const float4*)(C + (size_t)(kn + lrow) * D + kd + lcol4);
            Bs[lcol4 + 0][lrow] = b4.x;
            Bs[lcol4 + 1][lrow] = b4.y;
            Bs[lcol4 + 2][lrow] = b4.z;
            Bs[lcol4 + 3][lrow] = b4.w;
            __syncthreads();

            #pragma unroll
            for (int kk = 0; kk < BK; kk++) {
                float a[TM], b[TN];
                float4 av0 = *(const float4*)&As[kk][ty * TM];
                float4 av1 = *(const float4*)&As[kk][ty * TM + 4];
                a[0] = av0.x; a[1] = av0.y; a[2] = av0.z; a[3] = av0.w;
                a[4] = av1.x; a[5] = av1.y; a[6] = av1.z; a[7] = av1.w;
                float4 bv0 = *(const float4*)&Bs[kk][tx * TN];
                float4 bv1 = *(const float4*)&Bs[kk][tx * TN + 4];
                b[0] = bv0.x; b[1] = bv0.y; b[2] = bv0.z; b[3] = bv0.w;
                b[4] = bv1.x; b[5] = bv1.y; b[6] = bv1.z; b[7] = bv1.w;
                #pragma unroll
                for (int i = 0; i < TM; i++)
                    #pragma unroll
                    for (int j = 0; j < TN; j++)
                        acc[i][j] = fmaf(a[i], b[j], acc[i][j]);
            }
            __syncthreads();
        }

        // fold this column tile into the per-row running best
        #pragma unroll
        for (int j = 0; j < TN; j++) {
            int col = kn + tx * TN + j;
            float h = g_c2h[col];
            #pragma unroll
            for (int i = 0; i < TM; i++) {
                float v = acc[i][j] - h;
                unsigned u = __float_as_uint(v);
                u ^= (u & 0x80000000u) ? 0xFFFFFFFFu : 0x80000000u;
                unsigned long long key =
                    ((unsigned long long)u << 32) | (unsigned)(K - 1 - col);
                if (key > best[i]) best[i] = key;
            }
        }
    }

    // reduce the 16 column-group threads per row
    __shared__ unsigned long long sbest[BM];
    if (tid < BM) sbest[tid] = 0ULL;
    __syncthreads();
    #pragma unroll
    for (int i = 0; i < TM; i++)
        atomicMax(&sbest[ty * TM + i], best[i]);
    __syncthreads();
    if (tid < BM) {
        int k = K - 1 - (int)(sbest[tid] & 0xFFFFFFFFULL);
        g_labels[rowBase + tid] = k;
    }
}

// ---------------------------------------------------------------------------
// Segmented sum: sums[label[i]] += x_i ; msum[label[i]] += 1.
// grid = N, block = 256 (D/4 float4 per row -> one pass).
// ---------------------------------------------------------------------------
__global__ void accum_kernel(const float* __restrict__ X, int D) {
    int i = blockIdx.x;
    int lab = g_labels[i];
    const float4* row = (const float4*)(X + (size_t)i * D);
    float* dst = g_sums + (size_t)lab * D;
    for (int c = threadIdx.x; c < D / 4; c += blockDim.x) {
        float4 v = row[c];
        atomicAdd(&dst[4 * c + 0], v.x);
        atomicAdd(&dst[4 * c + 1], v.y);
        atomicAdd(&dst[4 * c + 2], v.z);
        atomicAdd(&dst[4 * c + 3], v.w);
    }
    if (threadIdx.x == 0) atomicAdd(&g_msum[lab], 1);
}

// ---------------------------------------------------------------------------
// EMA update. grid = K, block = 256.
// ---------------------------------------------------------------------------
__global__ void finalize_kernel(const float* __restrict__ centers,
                                const int* __restrict__ count,
                                float* __restrict__ out, int D) {
    int k = blockIdx.x;
    int cnt = g_msum[k];
    const float4* crow = (const float4*)(centers + (size_t)k * D);
    float4* orow = (float4*)(out + (size_t)k * D);
    if (cnt == 0) {
        for (int c = threadIdx.x; c < D / 4; c += blockDim.x) orow[c] = crow[c];
        return;
    }
    const float4* srow = (const float4*)(g_sums + (size_t)k * D);
    float cc  = (float)count[k];
    float cnf = (float)cnt;
    float cc_new = 0.5f * cc + 0.5f * cnf;       // CENTER_LR = 0.5
    float lr  = 1.0f / (cc_new + 1.0f);
    float om  = 1.0f - lr;
    float bscale = lr / cnf;                     // lr * (1/mask_sum)
    for (int c = threadIdx.x; c < D / 4; c += blockDim.x) {
        float4 cv = crow[c];
        float4 sv = srow[c];
        float4 o;
        o.x = om * cv.x + bscale * sv.x;
        o.y = om * cv.y + bscale * sv.y;
        o.z = om * cv.z + bscale * sv.z;
        o.w = om * cv.w + bscale * sv.w;
        orow[c] = o;
    }
}

// ---------------------------------------------------------------------------
extern "C" void kernel_launch(void* const* d_in, const int* in_sizes, int n_in,
                              void* d_out, int out_size) {
    const float* X     = (const float*)d_in[0];   // embedded [N, D]
    const float* C     = (const float*)d_in[1];   // centers  [K, D]
    const int*   count = (const int*)d_in[2];     // count    [K]
    float*       out   = (float*)d_out;           // new_centers [K, D]

    const int K = in_sizes[2];
    const int D = in_sizes[1] / K;
    const int N = in_sizes[0] / D;

    zero_kernel<<<(K * D + 255) / 256, 256>>>(K * D, K);
    c2h_kernel<<<K, 128>>>(C, D);
    gemm_argmax_kernel<<<N / BM, 256>>>(X, C, N, K, D);
    accum_kernel<<<N, 256>>>(X, D);
    finalize_kernel<<<K, 256>>>(C, count, out, D);
}

// round 5
// speedup vs baseline: 1.9779x; 1.9718x over previous
#include <cuda_runtime.h>
#include <mma.h>
#include <cstdint>

using namespace nvcuda;

// Problem shape (fixed by setup_inputs): N=16384, D=1024, K=1024
#define MAX_N 16384
#define MAX_K 1024
#define MAX_D 1024

// Scratch (static __device__ arrays — no allocation allowed)
__device__ float g_sums[MAX_K * MAX_D];   // batch cluster sums [K, D]
__device__ int   g_msum[MAX_K];           // per-cluster counts
__device__ float g_c2h [MAX_K];           // 0.5 * ||c_k||^2
__device__ int   g_labels[MAX_N];         // argmin labels

// ---------------------------------------------------------------------------
// cp.async helpers (sm_80+, valid at plain sm_100 target)
// ---------------------------------------------------------------------------
__device__ __forceinline__ uint32_t smem_u32(const void* p) {
    uint32_t a;
    asm("{ .reg .u64 t; cvta.to.shared.u64 t, %1; cvt.u32.u64 %0, t; }"
        : "=r"(a) : "l"(p));
    return a;
}
#define CP_ASYNC16(dst, src) \
    asm volatile("cp.async.cg.shared.global [%0], [%1], 16;" \
                 :: "r"(dst), "l"(src) : "memory")
#define CP_COMMIT() asm volatile("cp.async.commit_group;" ::: "memory")
#define CP_WAIT1()  asm volatile("cp.async.wait_group 1;" ::: "memory")
#define CP_WAIT0()  asm volatile("cp.async.wait_group 0;" ::: "memory")

// ---------------------------------------------------------------------------
// 0.5 * ||c_k||^2 per center. grid = K, block = 128.
// ---------------------------------------------------------------------------
__global__ void c2h_kernel(const float* __restrict__ C, int D) {
    int k = blockIdx.x;
    const float4* row = (const float4*)(C + (size_t)k * D);
    float s = 0.f;
    for (int i = threadIdx.x; i < D / 4; i += blockDim.x) {
        float4 v = row[i];
        s += v.x * v.x + v.y * v.y + v.z * v.z + v.w * v.w;
    }
    #pragma unroll
    for (int o = 16; o > 0; o >>= 1) s += __shfl_xor_sync(0xFFFFFFFFu, s, o);
    __shared__ float ws[32];
    int lane = threadIdx.x & 31, w = threadIdx.x >> 5;
    if (lane == 0) ws[w] = s;
    __syncthreads();
    if (threadIdx.x == 0) {
        float t = 0.f;
        int nw = blockDim.x >> 5;
        for (int i = 0; i < nw; i++) t += ws[i];
        g_c2h[k] = 0.5f * t;
    }
}

// ---------------------------------------------------------------------------
// Zero scratch.
// ---------------------------------------------------------------------------
__global__ void zero_kernel(int n_sums4, int K) {
    int i = blockIdx.x * blockDim.x + threadIdx.x;
    if (i < n_sums4) ((float4*)g_sums)[i] = make_float4(0.f, 0.f, 0.f, 0.f);
    if (i < K)       g_msum[i] = 0;
}

// ---------------------------------------------------------------------------
// tf32 wmma fused GEMM + argmax.
//   score[i,k] = x_i . c_k - 0.5||c_k||^2 ; labels[i] = argmax_k score
// One CTA per 128-row X tile; loops over 8 column tiles of 128 centers.
// BK=32 along D, cp.async double-buffered SMEM stages, wmma m16n16k8 tf32.
// Epilogue: store 128x128 scores to SMEM, per-row scan with key
//   (flip(score) << 32) | (K-1-k)  -> max-key == (min dist, then min k)
// which matches jnp.argmin's first-min tie-break exactly.
// ---------------------------------------------------------------------------
// SMEM map (dynamic, 73728 B):
//   stage0: A 0..18432 (128 x 36 fl), B 18432..36864
//   stage1: A 36864..55296,           B 55296..73728
//   score buffer (epilogue only): 0..67584 (128 x 132 fl) — overlaps stages
#define LDA 36
#define LDS_SCORE 132
#define STAGE_A(s) ((s) ? 36864u : 0u)
#define STAGE_B(s) ((s) ? 55296u : 18432u)
#define LBL_SMEM_BYTES 73728

__device__ __forceinline__ void load_tiles_async(
    uint32_t sbase, int stage, const float* __restrict__ X,
    const float* __restrict__ C, int rowBase, int colBase, int kd, int D, int tid) {
    uint32_t aS = sbase + STAGE_A(stage);
    uint32_t bS = sbase + STAGE_B(stage);
    #pragma unroll
    for (int i = 0; i < 4; i++) {
        int idx = tid + 256 * i;
        int row = idx >> 3, c4 = idx & 7;   // 8 float4 per 32-float row
        CP_ASYNC16(aS + (uint32_t)(row * (LDA * 4) + c4 * 16),
                   X + (size_t)(rowBase + row) * D + kd + c4 * 4);
    }
    #pragma unroll
    for (int i = 0; i < 4; i++) {
        int idx = tid + 256 * i;
        int row = idx >> 3, c4 = idx & 7;
        CP_ASYNC16(bS + (uint32_t)(row * (LDA * 4) + c4 * 16),
                   C + (size_t)(colBase + row) * D + kd + c4 * 4);
    }
}

__global__ __launch_bounds__(256, 1)
void labels_kernel(const float* __restrict__ X, const float* __restrict__ C,
                   int N, int K, int D) {
    extern __shared__ __align__(16) char dynsmem[];
    const uint32_t sbase = smem_u32(dynsmem);
    float* score_s = (float*)dynsmem;

    const int tid  = threadIdx.x;
    const int wid  = tid >> 5;
    const int warpM = wid >> 1;       // 0..3 -> rows warpM*32..+32
    const int warpN = wid & 1;        // 0..1 -> cols warpN*64..+64
    const int rowBase = blockIdx.x * 128;

    wmma::fragment<wmma::matrix_a, 16, 16, 8, wmma::precision::tf32, wmma::row_major> fa[2];
    wmma::fragment<wmma::matrix_b, 16, 16, 8, wmma::precision::tf32, wmma::col_major> fb[4];
    wmma::fragment<wmma::accumulator, 16, 16, 8, float> acc[2][4];

    unsigned long long best = 0ULL;   // any finite score beats key 0

    const int myRow  = tid >> 1;            // epilogue scan: 2 threads per row
    const int myCol0 = (tid & 1) * 64;

    for (int coltile = 0; coltile < 8; ++coltile) {
        const int colBase = coltile * 128;

        #pragma unroll
        for (int i = 0; i < 2; i++)
            #pragma unroll
            for (int j = 0; j < 4; j++) wmma::fill_fragment(acc[i][j], 0.0f);

        // prefetch ktile 0
        load_tiles_async(sbase, 0, X, C, rowBase, colBase, 0, D, tid);
        CP_COMMIT();

        for (int kt = 0; kt < 32; ++kt) {
            const int cur = kt & 1;
            if (kt + 1 < 32) {
                load_tiles_async(sbase, cur ^ 1, X, C, rowBase, colBase,
                                 (kt + 1) * 32, D, tid);
                CP_COMMIT();
                CP_WAIT1();
            } else {
                CP_WAIT0();
            }
            __syncthreads();

            const float* At = (const float*)(dynsmem + STAGE_A(cur));
            const float* Bt = (const float*)(dynsmem + STAGE_B(cur));
            #pragma unroll
            for (int ks = 0; ks < 4; ++ks) {
                #pragma unroll
                for (int i = 0; i < 2; i++)
                    wmma::load_matrix_sync(fa[i],
                        At + (warpM * 32 + i * 16) * LDA + ks * 8, LDA);
                #pragma unroll
                for (int j = 0; j < 4; j++)
                    wmma::load_matrix_sync(fb[j],
                        Bt + (warpN * 64 + j * 16) * LDA + ks * 8, LDA);
                #pragma unroll
                for (int i = 0; i < 2; i++)
                    #pragma unroll
                    for (int j = 0; j < 4; j++)
                        wmma::mma_sync(acc[i][j], fa[i], fb[j], acc[i][j]);
            }
            __syncthreads();
        }

        // ---- epilogue: scores -> SMEM -> per-row argmax fold ----
        #pragma unroll
        for (int i = 0; i < 2; i++)
            #pragma unroll
            for (int j = 0; j < 4; j++)
                wmma::store_matrix_sync(
                    score_s + (warpM * 32 + i * 16) * LDS_SCORE + warpN * 64 + j * 16,
                    acc[i][j], LDS_SCORE, wmma::mem_row_major);
        __syncthreads();

        {
            const float4* rp = (const float4*)(score_s + myRow * LDS_SCORE + myCol0);
            const float4* hp = (const float4*)(g_c2h + colBase + myCol0);
            #pragma unroll 4
            for (int q = 0; q < 16; q++) {
                float4 v4 = rp[q];
                float4 h4 = hp[q];
                int col = colBase + myCol0 + 4 * q;
                float vs[4] = { v4.x - h4.x, v4.y - h4.y, v4.z - h4.z, v4.w - h4.w };
                #pragma unroll
                for (int e = 0; e < 4; e++) {
                    unsigned u = __float_as_uint(vs[e]);
                    u ^= (u & 0x80000000u) ? 0xFFFFFFFFu : 0x80000000u;
                    unsigned long long key =
                        ((unsigned long long)u << 32) | (unsigned)(K - 1 - (col + e));
                    if (key > best) best = key;
                }
            }
        }
        __syncthreads();   // score buffer will be overwritten by next prefetch
    }

    // combine the two threads sharing a row, write label
    unsigned long long other = __shfl_xor_sync(0xFFFFFFFFu, best, 1);
    if (other > best) best = other;
    if ((tid & 1) == 0)
        g_labels[rowBase + myRow] = K - 1 - (int)(best & 0xFFFFFFFFULL);
}

// ---------------------------------------------------------------------------
// Segmented sum: sums[label[i]] += x_i ; msum[label[i]] += 1.
// ---------------------------------------------------------------------------
__global__ void accum_kernel(const float* __restrict__ X, int D) {
    int i = blockIdx.x;
    int lab = g_labels[i];
    const float4* row = (const float4*)(X + (size_t)i * D);
    float* dst = g_sums + (size_t)lab * D;
    for (int c = threadIdx.x; c < D / 4; c += blockDim.x) {
        float4 v = row[c];
        atomicAdd(&dst[4 * c + 0], v.x);
        atomicAdd(&dst[4 * c + 1], v.y);
        atomicAdd(&dst[4 * c + 2], v.z);
        atomicAdd(&dst[4 * c + 3], v.w);
    }
    if (threadIdx.x == 0) atomicAdd(&g_msum[lab], 1);
}

// ---------------------------------------------------------------------------
// EMA update. grid = K, block = 256.
// ---------------------------------------------------------------------------
__global__ void finalize_kernel(const float* __restrict__ centers,
                                const int* __restrict__ count,
                                float* __restrict__ out, int D) {
    int k = blockIdx.x;
    int cnt = g_msum[k];
    const float4* crow = (const float4*)(centers + (size_t)k * D);
    float4* orow = (float4*)(out + (size_t)k * D);
    if (cnt == 0) {
        for (int c = threadIdx.x; c < D / 4; c += blockDim.x) orow[c] = crow[c];
        return;
    }
    const float4* srow = (const float4*)(g_sums + (size_t)k * D);
    float cc  = (float)count[k];
    float cnf = (float)cnt;
    float cc_new = 0.5f * cc + 0.5f * cnf;       // CENTER_LR = 0.5
    float lr  = 1.0f / (cc_new + 1.0f);
    float om  = 1.0f - lr;
    float bscale = lr / cnf;
    for (int c = threadIdx.x; c < D / 4; c += blockDim.x) {
        float4 cv = crow[c];
        float4 sv = srow[c];
        float4 o;
        o.x = om * cv.x + bscale * sv.x;
        o.y = om * cv.y + bscale * sv.y;
        o.z = om * cv.z + bscale * sv.z;
        o.w = om * cv.w + bscale * sv.w;
        orow[c] = o;
    }
}

// ---------------------------------------------------------------------------
extern "C" void kernel_launch(void* const* d_in, const int* in_sizes, int n_in,
                              void* d_out, int out_size) {
    const float* X     = (const float*)d_in[0];   // embedded [N, D]
    const float* C     = (const float*)d_in[1];   // centers  [K, D]
    const int*   count = (const int*)d_in[2];     // count    [K]
    float*       out   = (float*)d_out;           // new_centers [K, D]

    const int K = in_sizes[2];
    const int D = in_sizes[1] / K;
    const int N = in_sizes[0] / D;

    static int smem_set = 0;
    if (!smem_set) {
        cudaFuncSetAttribute(labels_kernel,
                             cudaFuncAttributeMaxDynamicSharedMemorySize,
                             LBL_SMEM_BYTES);
        smem_set = 1;
    }

    zero_kernel<<<(K * D / 4 + 255) / 256, 256>>>(K * D / 4, K);
    c2h_kernel<<<K, 128>>>(C, D);
    labels_kernel<<<N / 128, 256, LBL_SMEM_BYTES>>>(X, C, N, K, D);
    accum_kernel<<<N, 256>>>(X, D);
    finalize_kernel<<<K, 256>>>(C, count, out, D);
}

// round 6
// speedup vs baseline: 4.8472x; 2.4507x over previous
#include <cuda_runtime.h>
#include <cuda_fp16.h>
#include <mma.h>
#include <cstdint>

using namespace nvcuda;

// Problem shape (fixed by setup_inputs): N=16384, D=1024, K=1024
#define MAX_N 16384
#define MAX_K 1024
#define MAX_D 1024

// Scratch (static __device__ arrays — no allocation allowed)
__device__ float  g_sums[MAX_K * MAX_D];   // batch cluster sums [K, D]
__device__ int    g_msum[MAX_K];           // per-cluster counts
__device__ float  g_c2h [MAX_K];           // 0.5 * ||c_k||^2
__device__ int    g_labels[MAX_N];         // argmin labels
__device__ __half g_Xh[MAX_N * MAX_D];     // fp16 copy of embedded
__device__ __half g_Ch[MAX_K * MAX_D];     // fp16 copy of centers

// ---------------------------------------------------------------------------
// cp.async helpers (sm_80+, valid at plain sm_100 target)
// ---------------------------------------------------------------------------
__device__ __forceinline__ uint32_t smem_u32(const void* p) {
    uint32_t a;
    asm("{ .reg .u64 t; cvta.to.shared.u64 t, %1; cvt.u32.u64 %0, t; }"
        : "=r"(a) : "l"(p));
    return a;
}
#define CP_ASYNC16(dst, src) \
    asm volatile("cp.async.cg.shared.global [%0], [%1], 16;" \
                 :: "r"(dst), "l"(src) : "memory")
#define CP_COMMIT() asm volatile("cp.async.commit_group;" ::: "memory")
#define CP_WAIT1()  asm volatile("cp.async.wait_group 1;" ::: "memory")
#define CP_WAIT0()  asm volatile("cp.async.wait_group 0;" ::: "memory")

// ---------------------------------------------------------------------------
// fp32 -> fp16 convert (vectorized). n4 = element count / 4.
// ---------------------------------------------------------------------------
__global__ void cvt_kernel(const float* __restrict__ src,
                           __half* __restrict__ dst, int n4) {
    int i = blockIdx.x * blockDim.x + threadIdx.x;
    if (i < n4) {
        float4 v = ((const float4*)src)[i];
        __half2 h0 = __floats2half2_rn(v.x, v.y);
        __half2 h1 = __floats2half2_rn(v.z, v.w);
        ((__half2*)dst)[2 * i + 0] = h0;
        ((__half2*)dst)[2 * i + 1] = h1;
    }
}

// ---------------------------------------------------------------------------
// 0.5 * ||c_k||^2 per center. grid = K, block = 128.
// ---------------------------------------------------------------------------
__global__ void c2h_kernel(const float* __restrict__ C, int D) {
    int k = blockIdx.x;
    const float4* row = (const float4*)(C + (size_t)k * D);
    float s = 0.f;
    for (int i = threadIdx.x; i < D / 4; i += blockDim.x) {
        float4 v = row[i];
        s += v.x * v.x + v.y * v.y + v.z * v.z + v.w * v.w;
    }
    #pragma unroll
    for (int o = 16; o > 0; o >>= 1) s += __shfl_xor_sync(0xFFFFFFFFu, s, o);
    __shared__ float ws[32];
    int lane = threadIdx.x & 31, w = threadIdx.x >> 5;
    if (lane == 0) ws[w] = s;
    __syncthreads();
    if (threadIdx.x == 0) {
        float t = 0.f;
        int nw = blockDim.x >> 5;
        for (int i = 0; i < nw; i++) t += ws[i];
        g_c2h[k] = 0.5f * t;
    }
}

// ---------------------------------------------------------------------------
// Zero scratch.
// ---------------------------------------------------------------------------
__global__ void zero_kernel(int n_sums4, int K) {
    int i = blockIdx.x * blockDim.x + threadIdx.x;
    if (i < n_sums4) ((float4*)g_sums)[i] = make_float4(0.f, 0.f, 0.f, 0.f);
    if (i < K)       g_msum[i] = 0;
}

// ---------------------------------------------------------------------------
// fp16 wmma fused GEMM + argmax.
//   score[i,k] = x_i . c_k - 0.5||c_k||^2 ; labels[i] = argmax_k score
// One CTA per 128-row X tile; loops over 8 column tiles of 128 centers.
// BK=64 along D, cp.async double-buffered fp16 stages, wmma m16n16k16.
// fp16 mantissa == tf32 mantissa (10 bits) -> same accuracy as tf32 path.
// Epilogue: 128x128 fp32 scores -> SMEM -> per-row scan with key
//   (flip(score) << 32) | (K-1-k)  -> max-key == (min dist, then min k),
// matching jnp.argmin's first-min tie-break exactly.
// ---------------------------------------------------------------------------
// SMEM map (dynamic, 73728 B):
//   stage0: A 0..18432 (128 rows x 72 halfs = 144 B/row), B 18432..36864
//   stage1: A 36864..55296,                               B 55296..73728
//   score buffer (epilogue only): 0..67584 (128 x 132 fl) — overlaps stages
#define LDA_H 72
#define LDS_SCORE 132
#define STAGE_A(s) ((s) ? 36864u : 0u)
#define STAGE_B(s) ((s) ? 55296u : 18432u)
#define LBL_SMEM_BYTES 73728

__device__ __forceinline__ void load_tiles_async(
    uint32_t sbase, int stage, const __half* __restrict__ Xh,
    const __half* __restrict__ Ch, int rowBase, int colBase, int kd, int D, int tid) {
    uint32_t aS = sbase + STAGE_A(stage);
    uint32_t bS = sbase + STAGE_B(stage);
    // 128 rows x 64 halfs (128 B/row) = 1024 x 16B chunks; 4 per thread.
    #pragma unroll
    for (int i = 0; i < 4; i++) {
        int idx = tid + 256 * i;
        int row = idx >> 3, c8 = idx & 7;   // 8 chunks of 8 halfs per row
        CP_ASYNC16(aS + (uint32_t)(row * (LDA_H * 2) + c8 * 16),
                   Xh + (size_t)(rowBase + row) * D + kd + c8 * 8);
    }
    #pragma unroll
    for (int i = 0; i < 4; i++) {
        int idx = tid + 256 * i;
        int row = idx >> 3, c8 = idx & 7;
        CP_ASYNC16(bS + (uint32_t)(row * (LDA_H * 2) + c8 * 16),
                   Ch + (size_t)(colBase + row) * D + kd + c8 * 8);
    }
}

__global__ __launch_bounds__(256, 1)
void labels_kernel(const __half* __restrict__ Xh, const __half* __restrict__ Ch,
                   int N, int K, int D) {
    extern __shared__ __align__(16) char dynsmem[];
    const uint32_t sbase = smem_u32(dynsmem);
    float* score_s = (float*)dynsmem;

    const int tid  = threadIdx.x;
    const int wid  = tid >> 5;
    const int warpM = wid >> 1;       // 0..3 -> rows warpM*32..+32
    const int warpN = wid & 1;        // 0..1 -> cols warpN*64..+64
    const int rowBase = blockIdx.x * 128;

    wmma::fragment<wmma::matrix_a, 16, 16, 16, __half, wmma::row_major> fa[2];
    wmma::fragment<wmma::matrix_b, 16, 16, 16, __half, wmma::col_major> fb[4];
    wmma::fragment<wmma::accumulator, 16, 16, 16, float> acc[2][4];

    unsigned long long best = 0ULL;   // any finite score beats key 0

    const int myRow  = tid >> 1;            // epilogue scan: 2 threads per row
    const int myCol0 = (tid & 1) * 64;

    const int NKT = D / 64;                 // 16 K-chunks

    for (int coltile = 0; coltile < 8; ++coltile) {
        const int colBase = coltile * 128;

        #pragma unroll
        for (int i = 0; i < 2; i++)
            #pragma unroll
            for (int j = 0; j < 4; j++) wmma::fill_fragment(acc[i][j], 0.0f);

        // prefetch ktile 0
        load_tiles_async(sbase, 0, Xh, Ch, rowBase, colBase, 0, D, tid);
        CP_COMMIT();

        for (int kt = 0; kt < NKT; ++kt) {
            const int cur = kt & 1;
            if (kt + 1 < NKT) {
                load_tiles_async(sbase, cur ^ 1, Xh, Ch, rowBase, colBase,
                                 (kt + 1) * 64, D, tid);
                CP_COMMIT();
                CP_WAIT1();
            } else {
                CP_WAIT0();
            }
            __syncthreads();

            const __half* At = (const __half*)(dynsmem + STAGE_A(cur));
            const __half* Bt = (const __half*)(dynsmem + STAGE_B(cur));
            #pragma unroll
            for (int ks = 0; ks < 4; ++ks) {   // 4 x k=16
                #pragma unroll
                for (int i = 0; i < 2; i++)
                    wmma::load_matrix_sync(fa[i],
                        At + (warpM * 32 + i * 16) * LDA_H + ks * 16, LDA_H);
                #pragma unroll
                for (int j = 0; j < 4; j++)
                    wmma::load_matrix_sync(fb[j],
                        Bt + (warpN * 64 + j * 16) * LDA_H + ks * 16, LDA_H);
                #pragma unroll
                for (int i = 0; i < 2; i++)
                    #pragma unroll
                    for (int j = 0; j < 4; j++)
                        wmma::mma_sync(acc[i][j], fa[i], fb[j], acc[i][j]);
            }
            __syncthreads();
        }

        // ---- epilogue: scores -> SMEM -> per-row argmax fold ----
        #pragma unroll
        for (int i = 0; i < 2; i++)
            #pragma unroll
            for (int j = 0; j < 4; j++)
                wmma::store_matrix_sync(
                    score_s + (warpM * 32 + i * 16) * LDS_SCORE + warpN * 64 + j * 16,
                    acc[i][j], LDS_SCORE, wmma::mem_row_major);
        __syncthreads();

        {
            const float4* rp = (const float4*)(score_s + myRow * LDS_SCORE + myCol0);
            const float4* hp = (const float4*)(g_c2h + colBase + myCol0);
            #pragma unroll 4
            for (int q = 0; q < 16; q++) {
                float4 v4 = rp[q];
                float4 h4 = hp[q];
                int col = colBase + myCol0 + 4 * q;
                float vs[4] = { v4.x - h4.x, v4.y - h4.y, v4.z - h4.z, v4.w - h4.w };
                #pragma unroll
                for (int e = 0; e < 4; e++) {
                    unsigned u = __float_as_uint(vs[e]);
                    u ^= (u & 0x80000000u) ? 0xFFFFFFFFu : 0x80000000u;
                    unsigned long long key =
                        ((unsigned long long)u << 32) | (unsigned)(K - 1 - (col + e));
                    if (key > best) best = key;
                }
            }
        }
        __syncthreads();   // score buffer will be overwritten by next prefetch
    }

    // combine the two threads sharing a row, write label
    unsigned long long other = __shfl_xor_sync(0xFFFFFFFFu, best, 1);
    if (other > best) best = other;
    if ((tid & 1) == 0)
        g_labels[rowBase + myRow] = K - 1 - (int)(best & 0xFFFFFFFFULL);
}

// ---------------------------------------------------------------------------
// Segmented sum: sums[label[i]] += x_i ; msum[label[i]] += 1.
// ---------------------------------------------------------------------------
__global__ void accum_kernel(const float* __restrict__ X, int D) {
    int i = blockIdx.x;
    int lab = g_labels[i];
    const float4* row = (const float4*)(X + (size_t)i * D);
    float* dst = g_sums + (size_t)lab * D;
    for (int c = threadIdx.x; c < D / 4; c += blockDim.x) {
        float4 v = row[c];
        atomicAdd(&dst[4 * c + 0], v.x);
        atomicAdd(&dst[4 * c + 1], v.y);
        atomicAdd(&dst[4 * c + 2], v.z);
        atomicAdd(&dst[4 * c + 3], v.w);
    }
    if (threadIdx.x == 0) atomicAdd(&g_msum[lab], 1);
}

// ---------------------------------------------------------------------------
// EMA update. grid = K, block = 256.
// ---------------------------------------------------------------------------
__global__ void finalize_kernel(const float* __restrict__ centers,
                                const int* __restrict__ count,
                                float* __restrict__ out, int D) {
    int k = blockIdx.x;
    int cnt = g_msum[k];
    const float4* crow = (const float4*)(centers + (size_t)k * D);
    float4* orow = (float4*)(out + (size_t)k * D);
    if (cnt == 0) {
        for (int c = threadIdx.x; c < D / 4; c += blockDim.x) orow[c] = crow[c];
        return;
    }
    const float4* srow = (const float4*)(g_sums + (size_t)k * D);
    float cc  = (float)count[k];
    float cnf = (float)cnt;
    float cc_new = 0.5f * cc + 0.5f * cnf;       // CENTER_LR = 0.5
    float lr  = 1.0f / (cc_new + 1.0f);
    float om  = 1.0f - lr;
    float bscale = lr / cnf;
    for (int c = threadIdx.x; c < D / 4; c += blockDim.x) {
        float4 cv = crow[c];
        float4 sv = srow[c];
        float4 o;
        o.x = om * cv.x + bscale * sv.x;
        o.y = om * cv.y + bscale * sv.y;
        o.z = om * cv.z + bscale * sv.z;
        o.w = om * cv.w + bscale * sv.w;
        orow[c] = o;
    }
}

// ---------------------------------------------------------------------------
extern "C" void kernel_launch(void* const* d_in, const int* in_sizes, int n_in,
                              void* d_out, int out_size) {
    const float* X     = (const float*)d_in[0];   // embedded [N, D]
    const float* C     = (const float*)d_in[1];   // centers  [K, D]
    const int*   count = (const int*)d_in[2];     // count    [K]
    float*       out   = (float*)d_out;           // new_centers [K, D]

    const int K = in_sizes[2];
    const int D = in_sizes[1] / K;
    const int N = in_sizes[0] / D;

    static int smem_set = 0;
    if (!smem_set) {
        cudaFuncSetAttribute(labels_kernel,
                             cudaFuncAttributeMaxDynamicSharedMemorySize,
                             LBL_SMEM_BYTES);
        smem_set = 1;
    }

    __half* Xh; cudaGetSymbolAddress((void**)&Xh, g_Xh);
    __half* Ch; cudaGetSymbolAddress((void**)&Ch, g_Ch);

    cvt_kernel<<<(N * D / 4 + 255) / 256, 256>>>(X, Xh, N * D / 4);
    cvt_kernel<<<(K * D / 4 + 255) / 256, 256>>>(C, Ch, K * D / 4);
    zero_kernel<<<(K * D / 4 + 255) / 256, 256>>>(K * D / 4, K);
    c2h_kernel<<<K, 128>>>(C, D);
    labels_kernel<<<N / 128, 256, LBL_SMEM_BYTES>>>(Xh, Ch, N, K, D);
    accum_kernel<<<N, 256>>>(X, D);
    finalize_kernel<<<K, 256>>>(C, count, out, D);
}

// round 7
// speedup vs baseline: 6.5904x; 1.3596x over previous
#include <cuda_runtime.h>
#include <cuda_fp16.h>
#include <mma.h>
#include <cstdint>

using namespace nvcuda;

// Problem shape (fixed by setup_inputs): N=16384, D=1024, K=1024
#define MAX_N 16384
#define MAX_K 1024
#define MAX_D 1024

// Scratch (static __device__ arrays — no allocation allowed)
__device__ float              g_sums[MAX_K * MAX_D];   // batch cluster sums [K, D]
__device__ int                g_msum[MAX_K];           // per-cluster counts
__device__ float              g_c2h [MAX_K];           // 0.5 * ||c_k||^2
__device__ int                g_labels[MAX_N];         // argmin labels
__device__ unsigned long long g_bestkey[MAX_N];        // per-row argmax keys
__device__ __half             g_Xh[MAX_N * MAX_D];     // fp16 copy of embedded
__device__ __half             g_Ch[MAX_K * MAX_D];     // fp16 copy of centers

// ---------------------------------------------------------------------------
// PTX helpers
// ---------------------------------------------------------------------------
__device__ __forceinline__ uint32_t smem_u32(const void* p) {
    uint32_t a;
    asm("{ .reg .u64 t; cvta.to.shared.u64 t, %1; cvt.u32.u64 %0, t; }"
        : "=r"(a) : "l"(p));
    return a;
}
#define CP_ASYNC16(dst, src) \
    asm volatile("cp.async.cg.shared.global [%0], [%1], 16;" \
                 :: "r"(dst), "l"(src) : "memory")
#define CP_COMMIT() asm volatile("cp.async.commit_group;" ::: "memory")
#define CP_WAIT1()  asm volatile("cp.async.wait_group 1;" ::: "memory")
#define CP_WAIT0()  asm volatile("cp.async.wait_group 0;" ::: "memory")

// Vectorized global float reduction (PTX ISA 8.1+, sm_90+)
__device__ __forceinline__ void red_add_v4(float* dst, float4 v) {
    asm volatile("red.global.add.v4.f32 [%0], {%1, %2, %3, %4};"
                 :: "l"(dst), "f"(v.x), "f"(v.y), "f"(v.z), "f"(v.w)
                 : "memory");
}

// ---------------------------------------------------------------------------
// fp32 -> fp16 convert (vectorized). n4 = element count / 4.
// ---------------------------------------------------------------------------
__global__ void cvt_kernel(const float* __restrict__ src,
                           __half* __restrict__ dst, int n4) {
    int i = blockIdx.x * blockDim.x + threadIdx.x;
    if (i < n4) {
        float4 v = ((const float4*)src)[i];
        ((__half2*)dst)[2 * i + 0] = __floats2half2_rn(v.x, v.y);
        ((__half2*)dst)[2 * i + 1] = __floats2half2_rn(v.z, v.w);
    }
}

// ---------------------------------------------------------------------------
// Fused: convert C row to fp16 AND compute 0.5*||c_k||^2. grid = K, block = 128.
// ---------------------------------------------------------------------------
__global__ void cvtC_c2h_kernel(const float* __restrict__ C,
                                __half* __restrict__ Ch, int D) {
    int k = blockIdx.x;
    const float4* row = (const float4*)(C + (size_t)k * D);
    __half2* drow = (__half2*)(Ch + (size_t)k * D);
    float s = 0.f;
    for (int i = threadIdx.x; i < D / 4; i += blockDim.x) {
        float4 v = row[i];
        drow[2 * i + 0] = __floats2half2_rn(v.x, v.y);
        drow[2 * i + 1] = __floats2half2_rn(v.z, v.w);
        s += v.x * v.x + v.y * v.y + v.z * v.z + v.w * v.w;
    }
    #pragma unroll
    for (int o = 16; o > 0; o >>= 1) s += __shfl_xor_sync(0xFFFFFFFFu, s, o);
    __shared__ float ws[4];
    int lane = threadIdx.x & 31, w = threadIdx.x >> 5;
    if (lane == 0) ws[w] = s;
    __syncthreads();
    if (threadIdx.x == 0)
        g_c2h[k] = 0.5f * (ws[0] + ws[1] + ws[2] + ws[3]);
}

// ---------------------------------------------------------------------------
// Zero scratch (sums, counts, argmax keys).
// ---------------------------------------------------------------------------
__global__ void zero_kernel(int n_sums4, int K, int N) {
    int i = blockIdx.x * blockDim.x + threadIdx.x;
    if (i < n_sums4) ((float4*)g_sums)[i] = make_float4(0.f, 0.f, 0.f, 0.f);
    if (i < K)       g_msum[i] = 0;
    if (i < N)       g_bestkey[i] = 0ULL;
}

// ---------------------------------------------------------------------------
// fp16 wmma fused GEMM + argmax, column-split for 2 CTAs/SM occupancy.
//   score[i,k] = x_i . c_k - 0.5||c_k||^2 ; labels[i] = argmax_k score
// grid = (N/128, 2): blockIdx.x = row tile, blockIdx.y = column half.
// Each CTA handles 4 column tiles of 128 centers; per-row winners merge
// via atomicMax on g_bestkey with the order-preserving key
//   (flip(score) << 32) | (K-1-k)  -> max == (min dist, then min k),
// matching jnp.argmin's first-min tie-break exactly.
// ---------------------------------------------------------------------------
#define LDA_H 72
#define LDS_SCORE 132
#define STAGE_A(s) ((s) ? 36864u : 0u)
#define STAGE_B(s) ((s) ? 55296u : 18432u)
#define LBL_SMEM_BYTES 73728

__device__ __forceinline__ void load_tiles_async(
    uint32_t sbase, int stage, const __half* __restrict__ Xh,
    const __half* __restrict__ Ch, int rowBase, int colBase, int kd, int D, int tid) {
    uint32_t aS = sbase + STAGE_A(stage);
    uint32_t bS = sbase + STAGE_B(stage);
    #pragma unroll
    for (int i = 0; i < 4; i++) {
        int idx = tid + 256 * i;
        int row = idx >> 3, c8 = idx & 7;   // 8 chunks of 8 halfs per 64-half row
        CP_ASYNC16(aS + (uint32_t)(row * (LDA_H * 2) + c8 * 16),
                   Xh + (size_t)(rowBase + row) * D + kd + c8 * 8);
    }
    #pragma unroll
    for (int i = 0; i < 4; i++) {
        int idx = tid + 256 * i;
        int row = idx >> 3, c8 = idx & 7;
        CP_ASYNC16(bS + (uint32_t)(row * (LDA_H * 2) + c8 * 16),
                   Ch + (size_t)(colBase + row) * D + kd + c8 * 8);
    }
}

__global__ __launch_bounds__(256, 2)
void labels_kernel(const __half* __restrict__ Xh, const __half* __restrict__ Ch,
                   int N, int K, int D) {
    extern __shared__ __align__(16) char dynsmem[];
    const uint32_t sbase = smem_u32(dynsmem);
    float* score_s = (float*)dynsmem;

    const int tid  = threadIdx.x;
    const int wid  = tid >> 5;
    const int warpM = wid >> 1;       // 0..3 -> rows warpM*32..+32
    const int warpN = wid & 1;        // 0..1 -> cols warpN*64..+64
    const int rowBase = blockIdx.x * 128;
    const int colGroup = blockIdx.y;  // 0 or 1 -> columns [cg*512, cg*512+512)

    wmma::fragment<wmma::matrix_a, 16, 16, 16, __half, wmma::row_major> fa[2];
    wmma::fragment<wmma::matrix_b, 16, 16, 16, __half, wmma::col_major> fb[4];
    wmma::fragment<wmma::accumulator, 16, 16, 16, float> acc[2][4];

    unsigned long long best = 0ULL;   // any finite score beats key 0

    const int myRow  = tid >> 1;            // epilogue scan: 2 threads per row
    const int myCol0 = (tid & 1) * 64;

    const int NKT = D / 64;                 // 16 K-chunks

    for (int coltile = 0; coltile < 4; ++coltile) {
        const int colBase = (colGroup * 4 + coltile) * 128;

        #pragma unroll
        for (int i = 0; i < 2; i++)
            #pragma unroll
            for (int j = 0; j < 4; j++) wmma::fill_fragment(acc[i][j], 0.0f);

        load_tiles_async(sbase, 0, Xh, Ch, rowBase, colBase, 0, D, tid);
        CP_COMMIT();

        for (int kt = 0; kt < NKT; ++kt) {
            const int cur = kt & 1;
            if (kt + 1 < NKT) {
                load_tiles_async(sbase, cur ^ 1, Xh, Ch, rowBase, colBase,
                                 (kt + 1) * 64, D, tid);
                CP_COMMIT();
                CP_WAIT1();
            } else {
                CP_WAIT0();
            }
            __syncthreads();

            const __half* At = (const __half*)(dynsmem + STAGE_A(cur));
            const __half* Bt = (const __half*)(dynsmem + STAGE_B(cur));
            #pragma unroll
            for (int ks = 0; ks < 4; ++ks) {   // 4 x k=16
                #pragma unroll
                for (int i = 0; i < 2; i++)
                    wmma::load_matrix_sync(fa[i],
                        At + (warpM * 32 + i * 16) * LDA_H + ks * 16, LDA_H);
                #pragma unroll
                for (int j = 0; j < 4; j++)
                    wmma::load_matrix_sync(fb[j],
                        Bt + (warpN * 64 + j * 16) * LDA_H + ks * 16, LDA_H);
                #pragma unroll
                for (int i = 0; i < 2; i++)
                    #pragma unroll
                    for (int j = 0; j < 4; j++)
                        wmma::mma_sync(acc[i][j], fa[i], fb[j], acc[i][j]);
            }
            __syncthreads();
        }

        // ---- epilogue: scores -> SMEM -> per-row argmax fold ----
        #pragma unroll
        for (int i = 0; i < 2; i++)
            #pragma unroll
            for (int j = 0; j < 4; j++)
                wmma::store_matrix_sync(
                    score_s + (warpM * 32 + i * 16) * LDS_SCORE + warpN * 64 + j * 16,
                    acc[i][j], LDS_SCORE, wmma::mem_row_major);
        __syncthreads();

        {
            const float4* rp = (const float4*)(score_s + myRow * LDS_SCORE + myCol0);
            const float4* hp = (const float4*)(g_c2h + colBase + myCol0);
            #pragma unroll 4
            for (int q = 0; q < 16; q++) {
                float4 v4 = rp[q];
                float4 h4 = hp[q];
                int col = colBase + myCol0 + 4 * q;
                float vs[4] = { v4.x - h4.x, v4.y - h4.y, v4.z - h4.z, v4.w - h4.w };
                #pragma unroll
                for (int e = 0; e < 4; e++) {
                    unsigned u = __float_as_uint(vs[e]);
                    u ^= (u & 0x80000000u) ? 0xFFFFFFFFu : 0x80000000u;
                    unsigned long long key =
                        ((unsigned long long)u << 32) | (unsigned)(K - 1 - (col + e));
                    if (key > best) best = key;
                }
            }
        }
        __syncthreads();   // score buffer will be overwritten by next prefetch
    }

    // combine the two threads sharing a row, merge across CTAs via atomicMax
    unsigned long long other = __shfl_xor_sync(0xFFFFFFFFu, best, 1);
    if (other > best) best = other;
    if ((tid & 1) == 0)
        atomicMax(&g_bestkey[rowBase + myRow], best);
}

// ---------------------------------------------------------------------------
// keys -> labels
// ---------------------------------------------------------------------------
__global__ void keys2labels_kernel(int N, int K) {
    int i = blockIdx.x * blockDim.x + threadIdx.x;
    if (i < N)
        g_labels[i] = K - 1 - (int)(g_bestkey[i] & 0xFFFFFFFFULL);
}

// ---------------------------------------------------------------------------
// Segmented sum via vectorized global reductions.
// grid = N, block = D/4 (=256): one red.v4 per thread.
// ---------------------------------------------------------------------------
__global__ void accum_kernel(const float* __restrict__ X, int D) {
    int i = blockIdx.x;
    int lab = g_labels[i];
    float4 v = ((const float4*)(X + (size_t)i * D))[threadIdx.x];
    red_add_v4(g_sums + (size_t)lab * D + threadIdx.x * 4, v);
    if (threadIdx.x == 0) atomicAdd(&g_msum[lab], 1);
}

// ---------------------------------------------------------------------------
// EMA update. grid = K, block = 256.
// ---------------------------------------------------------------------------
__global__ void finalize_kernel(const float* __restrict__ centers,
                                const int* __restrict__ count,
                                float* __restrict__ out, int D) {
    int k = blockIdx.x;
    int cnt = g_msum[k];
    const float4* crow = (const float4*)(centers + (size_t)k * D);
    float4* orow = (float4*)(out + (size_t)k * D);
    if (cnt == 0) {
        for (int c = threadIdx.x; c < D / 4; c += blockDim.x) orow[c] = crow[c];
        return;
    }
    const float4* srow = (const float4*)(g_sums + (size_t)k * D);
    float cc  = (float)count[k];
    float cnf = (float)cnt;
    float cc_new = 0.5f * cc + 0.5f * cnf;       // CENTER_LR = 0.5
    float lr  = 1.0f / (cc_new + 1.0f);
    float om  = 1.0f - lr;
    float bscale = lr / cnf;
    for (int c = threadIdx.x; c < D / 4; c += blockDim.x) {
        float4 cv = crow[c];
        float4 sv = srow[c];
        float4 o;
        o.x = om * cv.x + bscale * sv.x;
        o.y = om * cv.y + bscale * sv.y;
        o.z = om * cv.z + bscale * sv.z;
        o.w = om * cv.w + bscale * sv.w;
        orow[c] = o;
    }
}

// ---------------------------------------------------------------------------
extern "C" void kernel_launch(void* const* d_in, const int* in_sizes, int n_in,
                              void* d_out, int out_size) {
    const float* X     = (const float*)d_in[0];   // embedded [N, D]
    const float* C     = (const float*)d_in[1];   // centers  [K, D]
    const int*   count = (const int*)d_in[2];     // count    [K]
    float*       out   = (float*)d_out;           // new_centers [K, D]

    const int K = in_sizes[2];
    const int D = in_sizes[1] / K;
    const int N = in_sizes[0] / D;

    static int smem_set = 0;
    if (!smem_set) {
        cudaFuncSetAttribute(labels_kernel,
                             cudaFuncAttributeMaxDynamicSharedMemorySize,
                             LBL_SMEM_BYTES);
        smem_set = 1;
    }

    __half* Xh; cudaGetSymbolAddress((void**)&Xh, g_Xh);
    __half* Ch; cudaGetSymbolAddress((void**)&Ch, g_Ch);

    cvt_kernel<<<(N * D / 4 + 255) / 256, 256>>>(X, Xh, N * D / 4);
    cvtC_c2h_kernel<<<K, 128>>>(C, Ch, D);
    zero_kernel<<<(K * D / 4 + 255) / 256, 256>>>(K * D / 4, K, N);

    dim3 lgrid(N / 128, 2);
    labels_kernel<<<lgrid, 256, LBL_SMEM_BYTES>>>(Xh, Ch, N, K, D);

    keys2labels_kernel<<<(N + 255) / 256, 256>>>(N, K);
    accum_kernel<<<N, D / 4>>>(X, D);
    finalize_kernel<<<K, 256>>>(C, count, out, D);
}

// round 8
// speedup vs baseline: 6.7379x; 1.0224x over previous
#include <cuda_runtime.h>
#include <cuda_fp16.h>
#include <mma.h>
#include <cstdint>

using namespace nvcuda;

// Problem shape (fixed by setup_inputs): N=16384, D=1024, K=1024
#define MAX_N 16384
#define MAX_K 1024
#define MAX_D 1024

// Scratch (static __device__ arrays — no allocation allowed)
__device__ float              g_sums[MAX_K * MAX_D];   // batch cluster sums [K, D]
__device__ int                g_msum[MAX_K];           // per-cluster counts
__device__ float              g_c2h [MAX_K];           // 0.5 * ||c_k||^2
__device__ int                g_labels[MAX_N];         // argmin labels
__device__ unsigned long long g_bestkey[MAX_N];        // per-row argmax keys
__device__ __half             g_Xh[MAX_N * MAX_D];     // fp16 copy of embedded
__device__ __half             g_Ch[MAX_K * MAX_D];     // fp16 copy of centers

// ---------------------------------------------------------------------------
// PTX helpers
// ---------------------------------------------------------------------------
__device__ __forceinline__ uint32_t smem_u32(const void* p) {
    uint32_t a;
    asm("{ .reg .u64 t; cvta.to.shared.u64 t, %1; cvt.u32.u64 %0, t; }"
        : "=r"(a) : "l"(p));
    return a;
}
#define CP_ASYNC16(dst, src) \
    asm volatile("cp.async.cg.shared.global [%0], [%1], 16;" \
                 :: "r"(dst), "l"(src) : "memory")
#define CP_COMMIT() asm volatile("cp.async.commit_group;" ::: "memory")
#define CP_WAIT1()  asm volatile("cp.async.wait_group 1;" ::: "memory")
#define CP_WAIT0()  asm volatile("cp.async.wait_group 0;" ::: "memory")

// Vectorized global float reduction (PTX ISA 8.1+, sm_90+)
__device__ __forceinline__ void red_add_v4(float* dst, float4 v) {
    asm volatile("red.global.add.v4.f32 [%0], {%1, %2, %3, %4};"
                 :: "l"(dst), "f"(v.x), "f"(v.y), "f"(v.z), "f"(v.w)
                 : "memory");
}

// ---------------------------------------------------------------------------
// fp32 -> fp16 convert (vectorized). n4 = element count / 4.
// ---------------------------------------------------------------------------
__global__ void cvt_kernel(const float* __restrict__ src,
                           __half* __restrict__ dst, int n4) {
    int i = blockIdx.x * blockDim.x + threadIdx.x;
    if (i < n4) {
        float4 v = ((const float4*)src)[i];
        ((__half2*)dst)[2 * i + 0] = __floats2half2_rn(v.x, v.y);
        ((__half2*)dst)[2 * i + 1] = __floats2half2_rn(v.z, v.w);
    }
}

// ---------------------------------------------------------------------------
// Fused: convert C row to fp16 AND compute 0.5*||c_k||^2. grid = K, block = 128.
// ---------------------------------------------------------------------------
__global__ void cvtC_c2h_kernel(const float* __restrict__ C,
                                __half* __restrict__ Ch, int D) {
    int k = blockIdx.x;
    const float4* row = (const float4*)(C + (size_t)k * D);
    __half2* drow = (__half2*)(Ch + (size_t)k * D);
    float s = 0.f;
    for (int i = threadIdx.x; i < D / 4; i += blockDim.x) {
        float4 v = row[i];
        drow[2 * i + 0] = __floats2half2_rn(v.x, v.y);
        drow[2 * i + 1] = __floats2half2_rn(v.z, v.w);
        s += v.x * v.x + v.y * v.y + v.z * v.z + v.w * v.w;
    }
    #pragma unroll
    for (int o = 16; o > 0; o >>= 1) s += __shfl_xor_sync(0xFFFFFFFFu, s, o);
    __shared__ float ws[4];
    int lane = threadIdx.x & 31, w = threadIdx.x >> 5;
    if (lane == 0) ws[w] = s;
    __syncthreads();
    if (threadIdx.x == 0)
        g_c2h[k] = 0.5f * (ws[0] + ws[1] + ws[2] + ws[3]);
}

// ---------------------------------------------------------------------------
// Zero scratch (sums, counts, argmax keys).
// ---------------------------------------------------------------------------
__global__ void zero_kernel(int n_sums4, int K, int N) {
    int i = blockIdx.x * blockDim.x + threadIdx.x;
    if (i < n_sums4) ((float4*)g_sums)[i] = make_float4(0.f, 0.f, 0.f, 0.f);
    if (i < K)       g_msum[i] = 0;
    if (i < N)       g_bestkey[i] = 0ULL;
}

// ---------------------------------------------------------------------------
// fp16 wmma fused GEMM + argmax, column-split for 2 CTAs/SM occupancy.
//   score[i,k] = x_i . c_k - 0.5||c_k||^2 ; labels[i] = argmax_k score
// grid = (N/128, 2): blockIdx.x = row tile, blockIdx.y = column half.
// 3-stage cp.async pipeline, ONE __syncthreads per K-chunk:
//   iter kt: wait stage kt%3, sync, issue load into stage (kt+2)%3
//   (that buffer was computed at kt-1 -> safe after the sync), compute kt%3.
// Per-row winners merge via atomicMax on g_bestkey with the key
//   (flip(score) << 32) | (K-1-k)  -> max == (min dist, then min k),
// matching jnp.argmin's first-min tie-break exactly.
// ---------------------------------------------------------------------------
#define LDA_H 72
#define LDS_SCORE 132
#define STAGE_BYTES 36864u            // A(18432) + B(18432) per stage
#define STAGE_A(s) ((uint32_t)(s) * STAGE_BYTES)
#define STAGE_B(s) ((uint32_t)(s) * STAGE_BYTES + 18432u)
#define LBL_SMEM_BYTES (3 * 36864)    // 110592

__device__ __forceinline__ void load_tiles_async(
    uint32_t sbase, int stage, const __half* __restrict__ Xh,
    const __half* __restrict__ Ch, int rowBase, int colBase, int kd, int D, int tid) {
    uint32_t aS = sbase + STAGE_A(stage);
    uint32_t bS = sbase + STAGE_B(stage);
    #pragma unroll
    for (int i = 0; i < 4; i++) {
        int idx = tid + 256 * i;
        int row = idx >> 3, c8 = idx & 7;   // 8 chunks of 8 halfs per 64-half row
        CP_ASYNC16(aS + (uint32_t)(row * (LDA_H * 2) + c8 * 16),
                   Xh + (size_t)(rowBase + row) * D + kd + c8 * 8);
    }
    #pragma unroll
    for (int i = 0; i < 4; i++) {
        int idx = tid + 256 * i;
        int row = idx >> 3, c8 = idx & 7;
        CP_ASYNC16(bS + (uint32_t)(row * (LDA_H * 2) + c8 * 16),
                   Ch + (size_t)(colBase + row) * D + kd + c8 * 8);
    }
}

__global__ __launch_bounds__(256, 2)
void labels_kernel(const __half* __restrict__ Xh, const __half* __restrict__ Ch,
                   int N, int K, int D) {
    extern __shared__ __align__(16) char dynsmem[];
    const uint32_t sbase = smem_u32(dynsmem);
    float* score_s = (float*)dynsmem;

    const int tid  = threadIdx.x;
    const int wid  = tid >> 5;
    const int warpM = wid >> 1;       // 0..3 -> rows warpM*32..+32
    const int warpN = wid & 1;        // 0..1 -> cols warpN*64..+64
    const int rowBase = blockIdx.x * 128;
    const int colGroup = blockIdx.y;  // 0 or 1 -> columns [cg*512, cg*512+512)

    wmma::fragment<wmma::matrix_a, 16, 16, 16, __half, wmma::row_major> fa[2];
    wmma::fragment<wmma::matrix_b, 16, 16, 16, __half, wmma::col_major> fb[4];
    wmma::fragment<wmma::accumulator, 16, 16, 16, float> acc[2][4];

    unsigned long long best = 0ULL;   // any finite score beats key 0

    const int myRow  = tid >> 1;            // epilogue scan: 2 threads per row
    const int myCol0 = (tid & 1) * 64;

    const int NKT = D / 64;                 // 16 K-chunks

    for (int coltile = 0; coltile < 4; ++coltile) {
        const int colBase = (colGroup * 4 + coltile) * 128;

        #pragma unroll
        for (int i = 0; i < 2; i++)
            #pragma unroll
            for (int j = 0; j < 4; j++) wmma::fill_fragment(acc[i][j], 0.0f);

        // prologue: stages 0 and 1 in flight
        load_tiles_async(sbase, 0, Xh, Ch, rowBase, colBase, 0, D, tid);
        CP_COMMIT();
        load_tiles_async(sbase, 1, Xh, Ch, rowBase, colBase, 64, D, tid);
        CP_COMMIT();

        int s = 0;                          // stage holding chunk kt
        for (int kt = 0; kt < NKT; ++kt) {
            if (kt + 1 < NKT) { CP_WAIT1(); } else { CP_WAIT0(); }
            __syncthreads();                // stage s ready; all warps done with
                                            // the buffer about to be reloaded
            if (kt + 2 < NKT) {
                int ts = s + 2 >= 3 ? s - 1 : s + 2;     // (s+2) % 3
                load_tiles_async(sbase, ts, Xh, Ch, rowBase, colBase,
                                 (kt + 2) * 64, D, tid);
                CP_COMMIT();
            }

            const __half* At = (const __half*)(dynsmem + STAGE_A(s));
            const __half* Bt = (const __half*)(dynsmem + STAGE_B(s));
            #pragma unroll
            for (int ks = 0; ks < 4; ++ks) {   // 4 x k=16
                #pragma unroll
                for (int i = 0; i < 2; i++)
                    wmma::load_matrix_sync(fa[i],
                        At + (warpM * 32 + i * 16) * LDA_H + ks * 16, LDA_H);
                #pragma unroll
                for (int j = 0; j < 4; j++)
                    wmma::load_matrix_sync(fb[j],
                        Bt + (warpN * 64 + j * 16) * LDA_H + ks * 16, LDA_H);
                #pragma unroll
                for (int i = 0; i < 2; i++)
                    #pragma unroll
                    for (int j = 0; j < 4; j++)
                        wmma::mma_sync(acc[i][j], fa[i], fb[j], acc[i][j]);
            }
            s = (s + 1 == 3) ? 0 : s + 1;
        }

        // ---- epilogue: scores -> SMEM -> per-row argmax fold ----
        __syncthreads();   // last-stage compute done everywhere before overwrite
        #pragma unroll
        for (int i = 0; i < 2; i++)
            #pragma unroll
            for (int j = 0; j < 4; j++)
                wmma::store_matrix_sync(
                    score_s + (warpM * 32 + i * 16) * LDS_SCORE + warpN * 64 + j * 16,
                    acc[i][j], LDS_SCORE, wmma::mem_row_major);
        __syncthreads();

        {
            const float4* rp = (const float4*)(score_s + myRow * LDS_SCORE + myCol0);
            const float4* hp = (const float4*)(g_c2h + colBase + myCol0);
            #pragma unroll 4
            for (int q = 0; q < 16; q++) {
                float4 v4 = rp[q];
                float4 h4 = hp[q];
                int col = colBase + myCol0 + 4 * q;
                float vs[4] = { v4.x - h4.x, v4.y - h4.y, v4.z - h4.z, v4.w - h4.w };
                #pragma unroll
                for (int e = 0; e < 4; e++) {
                    unsigned u = __float_as_uint(vs[e]);
                    u ^= (u & 0x80000000u) ? 0xFFFFFFFFu : 0x80000000u;
                    unsigned long long key =
                        ((unsigned long long)u << 32) | (unsigned)(K - 1 - (col + e));
                    if (key > best) best = key;
                }
            }
        }
        __syncthreads();   // scan done before next coltile's prologue overwrites
    }

    // combine the two threads sharing a row, merge across CTAs via atomicMax
    unsigned long long other = __shfl_xor_sync(0xFFFFFFFFu, best, 1);
    if (other > best) best = other;
    if ((tid & 1) == 0)
        atomicMax(&g_bestkey[rowBase + myRow], best);
}

// ---------------------------------------------------------------------------
// keys -> labels
// ---------------------------------------------------------------------------
__global__ void keys2labels_kernel(int N, int K) {
    int i = blockIdx.x * blockDim.x + threadIdx.x;
    if (i < N)
        g_labels[i] = K - 1 - (int)(g_bestkey[i] & 0xFFFFFFFFULL);
}

// ---------------------------------------------------------------------------
// Segmented sum via vectorized global reductions.
// grid = N, block = D/4 (=256): one red.v4 per thread.
// ---------------------------------------------------------------------------
__global__ void accum_kernel(const float* __restrict__ X, int D) {
    int i = blockIdx.x;
    int lab = g_labels[i];
    float4 v = ((const float4*)(X + (size_t)i * D))[threadIdx.x];
    red_add_v4(g_sums + (size_t)lab * D + threadIdx.x * 4, v);
    if (threadIdx.x == 0) atomicAdd(&g_msum[lab], 1);
}

// ---------------------------------------------------------------------------
// EMA update. grid = K, block = 256.
// ---------------------------------------------------------------------------
__global__ void finalize_kernel(const float* __restrict__ centers,
                                const int* __restrict__ count,
                                float* __restrict__ out, int D) {
    int k = blockIdx.x;
    int cnt = g_msum[k];
    const float4* crow = (const float4*)(centers + (size_t)k * D);
    float4* orow = (float4*)(out + (size_t)k * D);
    if (cnt == 0) {
        for (int c = threadIdx.x; c < D / 4; c += blockDim.x) orow[c] = crow[c];
        return;
    }
    const float4* srow = (const float4*)(g_sums + (size_t)k * D);
    float cc  = (float)count[k];
    float cnf = (float)cnt;
    float cc_new = 0.5f * cc + 0.5f * cnf;       // CENTER_LR = 0.5
    float lr  = 1.0f / (cc_new + 1.0f);
    float om  = 1.0f - lr;
    float bscale = lr / cnf;
    for (int c = threadIdx.x; c < D / 4; c += blockDim.x) {
        float4 cv = crow[c];
        float4 sv = srow[c];
        float4 o;
        o.x = om * cv.x + bscale * sv.x;
        o.y = om * cv.y + bscale * sv.y;
        o.z = om * cv.z + bscale * sv.z;
        o.w = om * cv.w + bscale * sv.w;
        orow[c] = o;
    }
}

// ---------------------------------------------------------------------------
extern "C" void kernel_launch(void* const* d_in, const int* in_sizes, int n_in,
                              void* d_out, int out_size) {
    const float* X     = (const float*)d_in[0];   // embedded [N, D]
    const float* C     = (const float*)d_in[1];   // centers  [K, D]
    const int*   count = (const int*)d_in[2];     // count    [K]
    float*       out   = (float*)d_out;           // new_centers [K, D]

    const int K = in_sizes[2];
    const int D = in_sizes[1] / K;
    const int N = in_sizes[0] / D;

    static int smem_set = 0;
    if (!smem_set) {
        cudaFuncSetAttribute(labels_kernel,
                             cudaFuncAttributeMaxDynamicSharedMemorySize,
                             LBL_SMEM_BYTES);
        smem_set = 1;
    }

    __half* Xh; cudaGetSymbolAddress((void**)&Xh, g_Xh);
    __half* Ch; cudaGetSymbolAddress((void**)&Ch, g_Ch);

    cvt_kernel<<<(N * D / 4 + 255) / 256, 256>>>(X, Xh, N * D / 4);
    cvtC_c2h_kernel<<<K, 128>>>(C, Ch, D);
    zero_kernel<<<(K * D / 4 + 255) / 256, 256>>>(K * D / 4, K, N);

    dim3 lgrid(N / 128, 2);
    labels_kernel<<<lgrid, 256, LBL_SMEM_BYTES>>>(Xh, Ch, N, K, D);

    keys2labels_kernel<<<(N + 255) / 256, 256>>>(N, K);
    accum_kernel<<<N, D / 4>>>(X, D);
    finalize_kernel<<<K, 256>>>(C, count, out, D);
}

// round 9
// speedup vs baseline: 7.2465x; 1.0755x over previous
#include <cuda_runtime.h>
#include <cuda_fp16.h>
#include <cstdint>

// Problem shape (fixed by setup_inputs): N=16384, D=1024, K=1024
#define MAX_N 16384
#define MAX_K 1024
#define MAX_D 1024

// Scratch (static __device__ arrays — no allocation allowed)
__device__ float              g_sums[MAX_K * MAX_D];   // batch cluster sums [K, D]
__device__ int                g_msum[MAX_K];           // per-cluster counts
__device__ float              g_c2h [MAX_K];           // 0.5 * ||c_k||^2
__device__ unsigned long long g_bestkey[MAX_N];        // per-row argmax keys
__device__ __half             g_Xh[MAX_N * MAX_D];     // fp16 copy of embedded
__device__ __half             g_Ch[MAX_K * MAX_D];     // fp16 copy of centers

// ---------------------------------------------------------------------------
// PTX helpers
// ---------------------------------------------------------------------------
__device__ __forceinline__ uint32_t smem_u32(const void* p) {
    uint32_t a;
    asm("{ .reg .u64 t; cvta.to.shared.u64 t, %1; cvt.u32.u64 %0, t; }"
        : "=r"(a) : "l"(p));
    return a;
}
#define CP_ASYNC16(dst, src) \
    asm volatile("cp.async.cg.shared.global [%0], [%1], 16;" \
                 :: "r"(dst), "l"(src) : "memory")
#define CP_COMMIT() asm volatile("cp.async.commit_group;" ::: "memory")
#define CP_WAIT1()  asm volatile("cp.async.wait_group 1;" ::: "memory")
#define CP_WAIT0()  asm volatile("cp.async.wait_group 0;" ::: "memory")

__device__ __forceinline__ void ldm_x4(uint32_t* r, uint32_t addr) {
    asm volatile("ldmatrix.sync.aligned.m8n8.x4.shared.b16 {%0,%1,%2,%3}, [%4];"
                 : "=r"(r[0]), "=r"(r[1]), "=r"(r[2]), "=r"(r[3]) : "r"(addr));
}

__device__ __forceinline__ void mma16816(float* c, const uint32_t* a, const uint32_t* b) {
    asm volatile(
        "mma.sync.aligned.m16n8k16.row.col.f32.f16.f16.f32 "
        "{%0,%1,%2,%3}, {%4,%5,%6,%7}, {%8,%9}, {%0,%1,%2,%3};"
        : "+f"(c[0]), "+f"(c[1]), "+f"(c[2]), "+f"(c[3])
        : "r"(a[0]), "r"(a[1]), "r"(a[2]), "r"(a[3]), "r"(b[0]), "r"(b[1]));
}

// Vectorized global float reduction (PTX ISA 8.1+, sm_90+)
__device__ __forceinline__ void red_add_v4(float* dst, float4 v) {
    asm volatile("red.global.add.v4.f32 [%0], {%1, %2, %3, %4};"
                 :: "l"(dst), "f"(v.x), "f"(v.y), "f"(v.z), "f"(v.w)
                 : "memory");
}

// ---------------------------------------------------------------------------
// fp32 -> fp16 convert (vectorized). n4 = element count / 4.
// ---------------------------------------------------------------------------
__global__ void cvt_kernel(const float* __restrict__ src,
                           __half* __restrict__ dst, int n4) {
    int i = blockIdx.x * blockDim.x + threadIdx.x;
    if (i < n4) {
        float4 v = ((const float4*)src)[i];
        ((__half2*)dst)[2 * i + 0] = __floats2half2_rn(v.x, v.y);
        ((__half2*)dst)[2 * i + 1] = __floats2half2_rn(v.z, v.w);
    }
}

// ---------------------------------------------------------------------------
// Fused: convert C row to fp16 AND compute 0.5*||c_k||^2. grid = K, block = 128.
// ---------------------------------------------------------------------------
__global__ void cvtC_c2h_kernel(const float* __restrict__ C,
                                __half* __restrict__ Ch, int D) {
    int k = blockIdx.x;
    const float4* row = (const float4*)(C + (size_t)k * D);
    __half2* drow = (__half2*)(Ch + (size_t)k * D);
    float s = 0.f;
    for (int i = threadIdx.x; i < D / 4; i += blockDim.x) {
        float4 v = row[i];
        drow[2 * i + 0] = __floats2half2_rn(v.x, v.y);
        drow[2 * i + 1] = __floats2half2_rn(v.z, v.w);
        s += v.x * v.x + v.y * v.y + v.z * v.z + v.w * v.w;
    }
    #pragma unroll
    for (int o = 16; o > 0; o >>= 1) s += __shfl_xor_sync(0xFFFFFFFFu, s, o);
    __shared__ float ws[4];
    int lane = threadIdx.x & 31, w = threadIdx.x >> 5;
    if (lane == 0) ws[w] = s;
    __syncthreads();
    if (threadIdx.x == 0)
        g_c2h[k] = 0.5f * (ws[0] + ws[1] + ws[2] + ws[3]);
}

// ---------------------------------------------------------------------------
// Zero scratch (sums, counts, argmax keys).
// ---------------------------------------------------------------------------
__global__ void zero_kernel(int n_sums4, int K, int N) {
    int i = blockIdx.x * blockDim.x + threadIdx.x;
    if (i < n_sums4) ((float4*)g_sums)[i] = make_float4(0.f, 0.f, 0.f, 0.f);
    if (i < K)       g_msum[i] = 0;
    if (i < N)       g_bestkey[i] = 0ULL;
}

// ---------------------------------------------------------------------------
// Raw m16n8k16 fp16 fused GEMM + argmax.
//   score[i,k] = x_i . c_k - 0.5||c_k||^2 ; winner key -> g_bestkey[i]
// CTA tile 256x128, 8 warps as 4m x 2n, warp tile 64x64 (4 m-frags x 8 n-frags).
// 3-stage cp.async pipeline, one __syncthreads per K-chunk of 64.
// Epilogue fully in registers using the documented m16n8k16 accumulator
// layout; per-row winners merge via atomicMax with the order-preserving key
//   (flip(score) << 32) | (K-1-k)  -> max == (min dist, then min k),
// matching jnp.argmin's first-min tie-break exactly.
// ---------------------------------------------------------------------------
#define LDT 144u                                   // bytes per SMEM row (64h + pad)
#define A_STAGE_BYTES (256u * LDT)                 // 36864
#define B_STAGE_BYTES (128u * LDT)                 // 18432
#define STAGE_SZ (A_STAGE_BYTES + B_STAGE_BYTES)   // 55296
#define SA(s) ((uint32_t)(s) * STAGE_SZ)
#define SB(s) ((uint32_t)(s) * STAGE_SZ + A_STAGE_BYTES)
#define LBL_SMEM_BYTES (3 * 55296)                 // 165888

__device__ __forceinline__ void load_tiles_async(
    uint32_t sbase, int stage, const __half* __restrict__ Xh,
    const __half* __restrict__ Ch, int rowBase, int colBase, int kd, int D, int tid) {
    uint32_t aS = sbase + SA(stage);
    uint32_t bS = sbase + SB(stage);
    // A: 256 rows x 64 halfs = 2048 16B chunks; 8 per thread
    #pragma unroll
    for (int i = 0; i < 8; i++) {
        int idx = tid + 256 * i;
        int row = idx >> 3, c8 = idx & 7;
        CP_ASYNC16(aS + (uint32_t)(row * LDT + c8 * 16),
                   Xh + (size_t)(rowBase + row) * D + kd + c8 * 8);
    }
    // B: 128 rows x 64 halfs = 1024 chunks; 4 per thread
    #pragma unroll
    for (int i = 0; i < 4; i++) {
        int idx = tid + 256 * i;
        int row = idx >> 3, c8 = idx & 7;
        CP_ASYNC16(bS + (uint32_t)(row * LDT + c8 * 16),
                   Ch + (size_t)(colBase + row) * D + kd + c8 * 8);
    }
}

__global__ __launch_bounds__(256, 1)
void labels_kernel(const __half* __restrict__ Xh, const __half* __restrict__ Ch,
                   int N, int K, int D) {
    extern __shared__ __align__(16) char dynsmem[];
    const uint32_t sbase = smem_u32(dynsmem);

    const int tid   = threadIdx.x;
    const int wid   = tid >> 5;
    const int lane  = tid & 31;
    const int warpM = wid >> 1;      // 0..3 -> rows warpM*64..+64
    const int warpN = wid & 1;       // 0..1 -> cols warpN*64..+64
    const int rowBase  = blockIdx.x * 256;
    const int colGroup = blockIdx.y; // 0/1 -> columns [cg*512, cg*512+512)

    const int u = lane & 3;          // col pair selector within 8-col frag
    const int p = lane >> 2;         // row selector within 8-row half

    // ldmatrix lane-address offsets (within a stage)
    // A frag (16x16): lanes 0-15 -> rows 0-15 @k0, lanes 16-31 -> rows 0-15 @k8
    const uint32_t aOff = (uint32_t)(warpM * 64 + (lane & 15)) * LDT
                        + (uint32_t)(lane >> 4) * 16u;
    // B x4 covers 2 n-frags: g=lane>>3: n += (g>>1)*8, k += (g&1)*8
    const int g = lane >> 3;
    const uint32_t bOff = (uint32_t)(warpN * 64 + (g >> 1) * 8 + (lane & 7)) * LDT
                        + (uint32_t)(g & 1) * 16u;

    unsigned long long best[8];
    #pragma unroll
    for (int e = 0; e < 8; e++) best[e] = 0ULL;

    const int NKT = D / 64;          // 16 K-chunks

    for (int ct = 0; ct < 4; ++ct) {
        const int colBase = (colGroup * 4 + ct) * 128;

        float acc[4][8][4];
        #pragma unroll
        for (int i = 0; i < 4; i++)
            #pragma unroll
            for (int j = 0; j < 8; j++)
                #pragma unroll
                for (int e = 0; e < 4; e++) acc[i][j][e] = 0.f;

        load_tiles_async(sbase, 0, Xh, Ch, rowBase, colBase, 0, D, tid);
        CP_COMMIT();
        load_tiles_async(sbase, 1, Xh, Ch, rowBase, colBase, 64, D, tid);
        CP_COMMIT();

        int s = 0;
        for (int kt = 0; kt < NKT; ++kt) {
            if (kt + 1 < NKT) { CP_WAIT1(); } else { CP_WAIT0(); }
            __syncthreads();
            if (kt + 2 < NKT) {
                int ts = s + 2 >= 3 ? s - 1 : s + 2;   // (s+2) % 3
                load_tiles_async(sbase, ts, Xh, Ch, rowBase, colBase,
                                 (kt + 2) * 64, D, tid);
                CP_COMMIT();
            }

            const uint32_t aBase = sbase + SA(s) + aOff;
            const uint32_t bBase = sbase + SB(s) + bOff;
            #pragma unroll
            for (int ks = 0; ks < 4; ++ks) {       // 4 x k=16
                uint32_t a[4][4], b[4][4];
                #pragma unroll
                for (int i = 0; i < 4; i++)
                    ldm_x4(a[i], aBase + (uint32_t)(i * 16) * LDT + ks * 32);
                #pragma unroll
                for (int jp = 0; jp < 4; jp++)
                    ldm_x4(b[jp], bBase + (uint32_t)(jp * 16) * LDT + ks * 32);
                #pragma unroll
                for (int i = 0; i < 4; i++)
                    #pragma unroll
                    for (int j = 0; j < 8; j++)
                        mma16816(acc[i][j], a[i], &b[j >> 1][(j & 1) * 2]);
            }
            s = (s + 1 == 3) ? 0 : s + 1;
        }
        __syncthreads();   // all warps done before next coltile's prologue

        // ---- in-register epilogue ----
        // acc[i][j]: c0 -> (row p,   col 2u),   c1 -> (row p,   col 2u+1)
        //            c2 -> (row p+8, col 2u),   c3 -> (row p+8, col 2u+1)
        float2 h[8];
        #pragma unroll
        for (int j = 0; j < 8; j++)
            h[j] = *(const float2*)&g_c2h[colBase + warpN * 64 + j * 8 + u * 2];

        #pragma unroll
        for (int i = 0; i < 4; i++) {
            #pragma unroll
            for (int j = 0; j < 8; j++) {
                int col0 = colBase + warpN * 64 + j * 8 + u * 2;
                float v0 = acc[i][j][0] - h[j].x;   // row half 0, col0
                float v1 = acc[i][j][1] - h[j].y;   // row half 0, col0+1
                float v2 = acc[i][j][2] - h[j].x;   // row half 1, col0
                float v3 = acc[i][j][3] - h[j].y;   // row half 1, col0+1
                unsigned u0 = __float_as_uint(v0);
                unsigned u1 = __float_as_uint(v1);
                unsigned u2 = __float_as_uint(v2);
                unsigned u3 = __float_as_uint(v3);
                u0 ^= (u0 & 0x80000000u) ? 0xFFFFFFFFu : 0x80000000u;
                u1 ^= (u1 & 0x80000000u) ? 0xFFFFFFFFu : 0x80000000u;
                u2 ^= (u2 & 0x80000000u) ? 0xFFFFFFFFu : 0x80000000u;
                u3 ^= (u3 & 0x80000000u) ? 0xFFFFFFFFu : 0x80000000u;
                unsigned long long k0 =
                    ((unsigned long long)u0 << 32) | (unsigned)(K - 1 - col0);
                unsigned long long k1 =
                    ((unsigned long long)u1 << 32) | (unsigned)(K - 2 - col0);
                unsigned long long k2 =
                    ((unsigned long long)u2 << 32) | (unsigned)(K - 1 - col0);
                unsigned long long k3 =
                    ((unsigned long long)u3 << 32) | (unsigned)(K - 2 - col0);
                if (k0 > best[i * 2 + 0]) best[i * 2 + 0] = k0;
                if (k1 > best[i * 2 + 0]) best[i * 2 + 0] = k1;
                if (k2 > best[i * 2 + 1]) best[i * 2 + 1] = k2;
                if (k3 > best[i * 2 + 1]) best[i * 2 + 1] = k3;
            }
        }
    }

    // reduce across the 4 lanes of each quad (they hold different cols of the
    // same rows), then one atomicMax per row from lane u==0.
    #pragma unroll
    for (int e = 0; e < 8; e++) {
        unsigned long long v = best[e];
        unsigned long long o1 = __shfl_xor_sync(0xFFFFFFFFu, v, 1);
        if (o1 > v) v = o1;
        unsigned long long o2 = __shfl_xor_sync(0xFFFFFFFFu, v, 2);
        if (o2 > v) v = o2;
        if (u == 0) {
            int row = rowBase + warpM * 64 + (e >> 1) * 16 + (e & 1) * 8 + p;
            atomicMax(&g_bestkey[row], v);
        }
    }
}

// ---------------------------------------------------------------------------
// Segmented sum (label decoded from bestkey): sums[lab] += x_i; msum[lab]++.
// grid = N, block = D/4 (=256): one red.v4 per thread.
// ---------------------------------------------------------------------------
__global__ void accum_kernel(const float* __restrict__ X, int D, int K) {
    int i = blockIdx.x;
    int lab = K - 1 - (int)(g_bestkey[i] & 0xFFFFFFFFULL);
    float4 v = ((const float4*)(X + (size_t)i * D))[threadIdx.x];
    red_add_v4(g_sums + (size_t)lab * D + threadIdx.x * 4, v);
    if (threadIdx.x == 0) atomicAdd(&g_msum[lab], 1);
}

// ---------------------------------------------------------------------------
// EMA update. grid = K, block = 256.
// ---------------------------------------------------------------------------
__global__ void finalize_kernel(const float* __restrict__ centers,
                                const int* __restrict__ count,
                                float* __restrict__ out, int D) {
    int k = blockIdx.x;
    int cnt = g_msum[k];
    const float4* crow = (const float4*)(centers + (size_t)k * D);
    float4* orow = (float4*)(out + (size_t)k * D);
    if (cnt == 0) {
        for (int c = threadIdx.x; c < D / 4; c += blockDim.x) orow[c] = crow[c];
        return;
    }
    const float4* srow = (const float4*)(g_sums + (size_t)k * D);
    float cc  = (float)count[k];
    float cnf = (float)cnt;
    float cc_new = 0.5f * cc + 0.5f * cnf;       // CENTER_LR = 0.5
    float lr  = 1.0f / (cc_new + 1.0f);
    float om  = 1.0f - lr;
    float bscale = lr / cnf;
    for (int c = threadIdx.x; c < D / 4; c += blockDim.x) {
        float4 cv = crow[c];
        float4 sv = srow[c];
        float4 o;
        o.x = om * cv.x + bscale * sv.x;
        o.y = om * cv.y + bscale * sv.y;
        o.z = om * cv.z + bscale * sv.z;
        o.w = om * cv.w + bscale * sv.w;
        orow[c] = o;
    }
}

// ---------------------------------------------------------------------------
extern "C" void kernel_launch(void* const* d_in, const int* in_sizes, int n_in,
                              void* d_out, int out_size) {
    const float* X     = (const float*)d_in[0];   // embedded [N, D]
    const float* C     = (const float*)d_in[1];   // centers  [K, D]
    const int*   count = (const int*)d_in[2];     // count    [K]
    float*       out   = (float*)d_out;           // new_centers [K, D]

    const int K = in_sizes[2];
    const int D = in_sizes[1] / K;
    const int N = in_sizes[0] / D;

    static int smem_set = 0;
    if (!smem_set) {
        cudaFuncSetAttribute(labels_kernel,
                             cudaFuncAttributeMaxDynamicSharedMemorySize,
                             LBL_SMEM_BYTES);
        smem_set = 1;
    }

    __half* Xh; cudaGetSymbolAddress((void**)&Xh, g_Xh);
    __half* Ch; cudaGetSymbolAddress((void**)&Ch, g_Ch);

    cvt_kernel<<<(N * D / 4 + 255) / 256, 256>>>(X, Xh, N * D / 4);
    cvtC_c2h_kernel<<<K, 128>>>(C, Ch, D);
    zero_kernel<<<(K * D / 4 + 255) / 256, 256>>>(K * D / 4, K, N);

    dim3 lgrid(N / 256, 2);
    labels_kernel<<<lgrid, 256, LBL_SMEM_BYTES>>>(Xh, Ch, N, K, D);

    accum_kernel<<<N, D / 4>>>(X, D, K);
    finalize_kernel<<<K, 256>>>(C, count, out, D);
}

// round 10
// speedup vs baseline: 7.3920x; 1.0201x over previous
#include <cuda_runtime.h>
#include <cuda_fp16.h>
#include <cstdint>

// Problem shape (fixed by setup_inputs): N=16384, D=1024, K=1024
#define MAX_N 16384
#define MAX_K 1024
#define MAX_D 1024

// Scratch (static __device__ arrays — no allocation allowed)
__device__ float              g_sums[MAX_K * MAX_D];   // batch cluster sums [K, D]
__device__ int                g_msum[MAX_K];           // per-cluster counts
__device__ float              g_c2h [MAX_K];           // 0.5 * ||c_k||^2
__device__ unsigned long long g_bestkey[MAX_N];        // per-row argmax keys
__device__ __half             g_Xh[MAX_N * MAX_D];     // fp16 copy of embedded
__device__ __half             g_Ch[MAX_K * MAX_D];     // fp16 copy of centers

// ---------------------------------------------------------------------------
// PTX helpers
// ---------------------------------------------------------------------------
__device__ __forceinline__ uint32_t smem_u32(const void* p) {
    uint32_t a;
    asm("{ .reg .u64 t; cvta.to.shared.u64 t, %1; cvt.u32.u64 %0, t; }"
        : "=r"(a) : "l"(p));
    return a;
}
#define CP_ASYNC16(dst, src) \
    asm volatile("cp.async.cg.shared.global [%0], [%1], 16;" \
                 :: "r"(dst), "l"(src) : "memory")
#define CP_COMMIT() asm volatile("cp.async.commit_group;" ::: "memory")
#define CP_WAIT1()  asm volatile("cp.async.wait_group 1;" ::: "memory")
#define CP_WAIT0()  asm volatile("cp.async.wait_group 0;" ::: "memory")

__device__ __forceinline__ void ldm_x4(uint32_t* r, uint32_t addr) {
    asm volatile("ldmatrix.sync.aligned.m8n8.x4.shared.b16 {%0,%1,%2,%3}, [%4];"
                 : "=r"(r[0]), "=r"(r[1]), "=r"(r[2]), "=r"(r[3]) : "r"(addr));
}

__device__ __forceinline__ void mma16816(float* c, const uint32_t* a, const uint32_t* b) {
    asm volatile(
        "mma.sync.aligned.m16n8k16.row.col.f32.f16.f16.f32 "
        "{%0,%1,%2,%3}, {%4,%5,%6,%7}, {%8,%9}, {%0,%1,%2,%3};"
        : "+f"(c[0]), "+f"(c[1]), "+f"(c[2]), "+f"(c[3])
        : "r"(a[0]), "r"(a[1]), "r"(a[2]), "r"(a[3]), "r"(b[0]), "r"(b[1]));
}

// Vectorized global float reduction (PTX ISA 8.1+, sm_90+)
__device__ __forceinline__ void red_add_v4(float* dst, float4 v) {
    asm volatile("red.global.add.v4.f32 [%0], {%1, %2, %3, %4};"
                 :: "l"(dst), "f"(v.x), "f"(v.y), "f"(v.z), "f"(v.w)
                 : "memory");
}

// ---------------------------------------------------------------------------
// fp32 -> fp16 convert for X, fused with zeroing of sums/msum/bestkey.
// n4 = N*D/4 (largest of the zero ranges is K*D/4 < n4).
// ---------------------------------------------------------------------------
__global__ void cvtX_zero_kernel(const float* __restrict__ src,
                                 __half* __restrict__ dst,
                                 int n4, int n_sums4, int K, int N) {
    int i = blockIdx.x * blockDim.x + threadIdx.x;
    if (i < n4) {
        float4 v = ((const float4*)src)[i];
        ((__half2*)dst)[2 * i + 0] = __floats2half2_rn(v.x, v.y);
        ((__half2*)dst)[2 * i + 1] = __floats2half2_rn(v.z, v.w);
    }
    if (i < n_sums4) ((float4*)g_sums)[i] = make_float4(0.f, 0.f, 0.f, 0.f);
    if (i < K)       g_msum[i] = 0;
    if (i < N)       g_bestkey[i] = 0ULL;
}

// ---------------------------------------------------------------------------
// Fused: convert C row to fp16 AND compute 0.5*||c_k||^2. grid = K, block = 128.
// ---------------------------------------------------------------------------
__global__ void cvtC_c2h_kernel(const float* __restrict__ C,
                                __half* __restrict__ Ch, int D) {
    int k = blockIdx.x;
    const float4* row = (const float4*)(C + (size_t)k * D);
    __half2* drow = (__half2*)(Ch + (size_t)k * D);
    float s = 0.f;
    for (int i = threadIdx.x; i < D / 4; i += blockDim.x) {
        float4 v = row[i];
        drow[2 * i + 0] = __floats2half2_rn(v.x, v.y);
        drow[2 * i + 1] = __floats2half2_rn(v.z, v.w);
        s += v.x * v.x + v.y * v.y + v.z * v.z + v.w * v.w;
    }
    #pragma unroll
    for (int o = 16; o > 0; o >>= 1) s += __shfl_xor_sync(0xFFFFFFFFu, s, o);
    __shared__ float ws[4];
    int lane = threadIdx.x & 31, w = threadIdx.x >> 5;
    if (lane == 0) ws[w] = s;
    __syncthreads();
    if (threadIdx.x == 0)
        g_c2h[k] = 0.5f * (ws[0] + ws[1] + ws[2] + ws[3]);
}

// ---------------------------------------------------------------------------
// Raw m16n8k16 fp16 fused GEMM + argmax.
//   score[i,k] = x_i . c_k - 0.5||c_k||^2 ; winner key -> g_bestkey[i]
// CTA tile 256x128, 512 threads, 16 warps as 8m x 2n, warp tile 32x64
// (2 m-frags x 8 n-frags). 3-stage cp.async pipeline, one sync per K-chunk.
// In-register epilogue; per-row winners merge via atomicMax with the key
//   (flip(score) << 32) | (K-1-k)  -> max == (min dist, then min k),
// matching jnp.argmin's first-min tie-break exactly.
// ---------------------------------------------------------------------------
#define LDT 144u                                   // bytes per SMEM row (64h + pad)
#define A_STAGE_BYTES (256u * LDT)                 // 36864
#define B_STAGE_BYTES (128u * LDT)                 // 18432
#define STAGE_SZ (A_STAGE_BYTES + B_STAGE_BYTES)   // 55296
#define SA(s) ((uint32_t)(s) * STAGE_SZ)
#define SB(s) ((uint32_t)(s) * STAGE_SZ + A_STAGE_BYTES)
#define LBL_SMEM_BYTES (3 * 55296)                 // 165888
#define NTHR 512

__device__ __forceinline__ void load_tiles_async(
    uint32_t sbase, int stage, const __half* __restrict__ Xh,
    const __half* __restrict__ Ch, int rowBase, int colBase, int kd, int D, int tid) {
    uint32_t aS = sbase + SA(stage);
    uint32_t bS = sbase + SB(stage);
    // A: 256 rows x 64 halfs = 2048 16B chunks; 4 per thread
    #pragma unroll
    for (int i = 0; i < 4; i++) {
        int idx = tid + NTHR * i;
        int row = idx >> 3, c8 = idx & 7;
        CP_ASYNC16(aS + (uint32_t)(row * LDT + c8 * 16),
                   Xh + (size_t)(rowBase + row) * D + kd + c8 * 8);
    }
    // B: 128 rows x 64 halfs = 1024 chunks; 2 per thread
    #pragma unroll
    for (int i = 0; i < 2; i++) {
        int idx = tid + NTHR * i;
        int row = idx >> 3, c8 = idx & 7;
        CP_ASYNC16(bS + (uint32_t)(row * LDT + c8 * 16),
                   Ch + (size_t)(colBase + row) * D + kd + c8 * 8);
    }
}

__global__ __launch_bounds__(NTHR, 1)
void labels_kernel(const __half* __restrict__ Xh, const __half* __restrict__ Ch,
                   int N, int K, int D) {
    extern __shared__ __align__(16) char dynsmem[];
    const uint32_t sbase = smem_u32(dynsmem);

    const int tid   = threadIdx.x;
    const int wid   = tid >> 5;
    const int lane  = tid & 31;
    const int warpM = wid >> 1;      // 0..7 -> rows warpM*32..+32
    const int warpN = wid & 1;       // 0..1 -> cols warpN*64..+64
    const int rowBase  = blockIdx.x * 256;
    const int colGroup = blockIdx.y; // 0/1 -> columns [cg*512, cg*512+512)

    const int u = lane & 3;          // col pair selector within 8-col frag
    const int p = lane >> 2;         // row selector within 8-row half

    // ldmatrix lane-address offsets (within a stage)
    // A frag (16x16): lanes 0-15 -> rows 0-15 @k0, lanes 16-31 -> rows @k8
    const uint32_t aOff = (uint32_t)(warpM * 32 + (lane & 15)) * LDT
                        + (uint32_t)(lane >> 4) * 16u;
    // B x4 covers 2 n-frags: g=lane>>3: n += (g>>1)*8, k += (g&1)*8
    const int g = lane >> 3;
    const uint32_t bOff = (uint32_t)(warpN * 64 + (g >> 1) * 8 + (lane & 7)) * LDT
                        + (uint32_t)(g & 1) * 16u;

    unsigned long long best[4];
    #pragma unroll
    for (int e = 0; e < 4; e++) best[e] = 0ULL;

    const int NKT = D / 64;          // 16 K-chunks

    for (int ct = 0; ct < 4; ++ct) {
        const int colBase = (colGroup * 4 + ct) * 128;

        float acc[2][8][4];
        #pragma unroll
        for (int i = 0; i < 2; i++)
            #pragma unroll
            for (int j = 0; j < 8; j++)
                #pragma unroll
                for (int e = 0; e < 4; e++) acc[i][j][e] = 0.f;

        load_tiles_async(sbase, 0, Xh, Ch, rowBase, colBase, 0, D, tid);
        CP_COMMIT();
        load_tiles_async(sbase, 1, Xh, Ch, rowBase, colBase, 64, D, tid);
        CP_COMMIT();

        int s = 0;
        for (int kt = 0; kt < NKT; ++kt) {
            if (kt + 1 < NKT) { CP_WAIT1(); } else { CP_WAIT0(); }
            __syncthreads();
            if (kt + 2 < NKT) {
                int ts = s + 2 >= 3 ? s - 1 : s + 2;   // (s+2) % 3
                load_tiles_async(sbase, ts, Xh, Ch, rowBase, colBase,
                                 (kt + 2) * 64, D, tid);
                CP_COMMIT();
            }

            const uint32_t aBase = sbase + SA(s) + aOff;
            const uint32_t bBase = sbase + SB(s) + bOff;
            #pragma unroll
            for (int ks = 0; ks < 4; ++ks) {       // 4 x k=16
                uint32_t a[2][4], b[4][4];
                #pragma unroll
                for (int i = 0; i < 2; i++)
                    ldm_x4(a[i], aBase + (uint32_t)(i * 16) * LDT + ks * 32);
                #pragma unroll
                for (int jp = 0; jp < 4; jp++)
                    ldm_x4(b[jp], bBase + (uint32_t)(jp * 16) * LDT + ks * 32);
                #pragma unroll
                for (int i = 0; i < 2; i++)
                    #pragma unroll
                    for (int j = 0; j < 8; j++)
                        mma16816(acc[i][j], a[i], &b[j >> 1][(j & 1) * 2]);
            }
            s = (s + 1 == 3) ? 0 : s + 1;
        }
        __syncthreads();   // all warps done before next coltile's prologue

        // ---- in-register epilogue ----
        // acc[i][j]: c0 -> (row p,   col 2u),   c1 -> (row p,   col 2u+1)
        //            c2 -> (row p+8, col 2u),   c3 -> (row p+8, col 2u+1)
        #pragma unroll
        for (int i = 0; i < 2; i++) {
            #pragma unroll
            for (int j = 0; j < 8; j++) {
                int col0 = colBase + warpN * 64 + j * 8 + u * 2;
                float2 h = *(const float2*)&g_c2h[col0];
                float v0 = acc[i][j][0] - h.x;   // row half 0, col0
                float v1 = acc[i][j][1] - h.y;   // row half 0, col0+1
                float v2 = acc[i][j][2] - h.x;   // row half 1, col0
                float v3 = acc[i][j][3] - h.y;   // row half 1, col0+1
                unsigned u0 = __float_as_uint(v0);
                unsigned u1 = __float_as_uint(v1);
                unsigned u2 = __float_as_uint(v2);
                unsigned u3 = __float_as_uint(v3);
                u0 ^= (u0 & 0x80000000u) ? 0xFFFFFFFFu : 0x80000000u;
                u1 ^= (u1 & 0x80000000u) ? 0xFFFFFFFFu : 0x80000000u;
                u2 ^= (u2 & 0x80000000u) ? 0xFFFFFFFFu : 0x80000000u;
                u3 ^= (u3 & 0x80000000u) ? 0xFFFFFFFFu : 0x80000000u;
                unsigned long long k0 =
                    ((unsigned long long)u0 << 32) | (unsigned)(K - 1 - col0);
                unsigned long long k1 =
                    ((unsigned long long)u1 << 32) | (unsigned)(K - 2 - col0);
                unsigned long long k2 =
                    ((unsigned long long)u2 << 32) | (unsigned)(K - 1 - col0);
                unsigned long long k3 =
                    ((unsigned long long)u3 << 32) | (unsigned)(K - 2 - col0);
                if (k0 > best[i * 2 + 0]) best[i * 2 + 0] = k0;
                if (k1 > best[i * 2 + 0]) best[i * 2 + 0] = k1;
                if (k2 > best[i * 2 + 1]) best[i * 2 + 1] = k2;
                if (k3 > best[i * 2 + 1]) best[i * 2 + 1] = k3;
            }
        }
    }

    // reduce across the 4 lanes of each quad (they hold different cols of the
    // same rows), then one atomicMax per row from lane u==0.
    #pragma unroll
    for (int e = 0; e < 4; e++) {
        unsigned long long v = best[e];
        unsigned long long o1 = __shfl_xor_sync(0xFFFFFFFFu, v, 1);
        if (o1 > v) v = o1;
        unsigned long long o2 = __shfl_xor_sync(0xFFFFFFFFu, v, 2);
        if (o2 > v) v = o2;
        if (u == 0) {
            int row = rowBase + warpM * 32 + (e >> 1) * 16 + (e & 1) * 8 + p;
            atomicMax(&g_bestkey[row], v);
        }
    }
}

// ---------------------------------------------------------------------------
// Segmented sum (label decoded from bestkey): sums[lab] += x_i; msum[lab]++.
// grid = N, block = D/4 (=256): one red.v4 per thread.
// ---------------------------------------------------------------------------
__global__ void accum_kernel(const float* __restrict__ X, int D, int K) {
    int i = blockIdx.x;
    int lab = K - 1 - (int)(g_bestkey[i] & 0xFFFFFFFFULL);
    float4 v = ((const float4*)(X + (size_t)i * D))[threadIdx.x];
    red_add_v4(g_sums + (size_t)lab * D + threadIdx.x * 4, v);
    if (threadIdx.x == 0) atomicAdd(&g_msum[lab], 1);
}

// ---------------------------------------------------------------------------
// EMA update. grid = K, block = 256.
// ---------------------------------------------------------------------------
__global__ void finalize_kernel(const float* __restrict__ centers,
                                const int* __restrict__ count,
                                float* __restrict__ out, int D) {
    int k = blockIdx.x;
    int cnt = g_msum[k];
    const float4* crow = (const float4*)(centers + (size_t)k * D);
    float4* orow = (float4*)(out + (size_t)k * D);
    if (cnt == 0) {
        for (int c = threadIdx.x; c < D / 4; c += blockDim.x) orow[c] = crow[c];
        return;
    }
    const float4* srow = (const float4*)(g_sums + (size_t)k * D);
    float cc  = (float)count[k];
    float cnf = (float)cnt;
    float cc_new = 0.5f * cc + 0.5f * cnf;       // CENTER_LR = 0.5
    float lr  = 1.0f / (cc_new + 1.0f);
    float om  = 1.0f - lr;
    float bscale = lr / cnf;
    for (int c = threadIdx.x; c < D / 4; c += blockDim.x) {
        float4 cv = crow[c];
        float4 sv = srow[c];
        float4 o;
        o.x = om * cv.x + bscale * sv.x;
        o.y = om * cv.y + bscale * sv.y;
        o.z = om * cv.z + bscale * sv.z;
        o.w = om * cv.w + bscale * sv.w;
        orow[c] = o;
    }
}

// ---------------------------------------------------------------------------
extern "C" void kernel_launch(void* const* d_in, const int* in_sizes, int n_in,
                              void* d_out, int out_size) {
    const float* X     = (const float*)d_in[0];   // embedded [N, D]
    const float* C     = (const float*)d_in[1];   // centers  [K, D]
    const int*   count = (const int*)d_in[2];     // count    [K]
    float*       out   = (float*)d_out;           // new_centers [K, D]

    const int K = in_sizes[2];
    const int D = in_sizes[1] / K;
    const int N = in_sizes[0] / D;

    static int smem_set = 0;
    if (!smem_set) {
        cudaFuncSetAttribute(labels_kernel,
                             cudaFuncAttributeMaxDynamicSharedMemorySize,
                             LBL_SMEM_BYTES);
        smem_set = 1;
    }

    __half* Xh; cudaGetSymbolAddress((void**)&Xh, g_Xh);
    __half* Ch; cudaGetSymbolAddress((void**)&Ch, g_Ch);

    cvtX_zero_kernel<<<(N * D / 4 + 255) / 256, 256>>>(X, Xh, N * D / 4,
                                                       K * D / 4, K, N);
    cvtC_c2h_kernel<<<K, 128>>>(C, Ch, D);

    dim3 lgrid(N / 256, 2);
    labels_kernel<<<lgrid, NTHR, LBL_SMEM_BYTES>>>(Xh, Ch, N, K, D);

    accum_kernel<<<N, D / 4>>>(X, D, K);
    finalize_kernel<<<K, 256>>>(C, count, out, D);
}